// round 1
// baseline (speedup 1.0000x reference)
#include <cuda_runtime.h>

#define S_LEN 2048
#define HID   1024
#define NHEAD 16
#define HDIM  64
#define BATCH 2
#define MROWS (BATCH * S_LEN)   // 4096

// Scratch (allocation-free rule: __device__ globals)
__device__ float g_qkv[(size_t)MROWS * 3 * HID];   // [4096, 3072]
__device__ float g_ctx[(size_t)MROWS * HID];       // [4096, 1024]

// ---------------------------------------------------------------------------
// SGEMM: C[M,N] = A[M,K] * B[K,N] + bias[N]
// BM=BN=128, BK=16, 256 threads, 8x8 microtile per thread.
// ---------------------------------------------------------------------------
#define BM 128
#define BN 128
#define BK 16

__global__ __launch_bounds__(256) void sgemm_bias(
    const float* __restrict__ A, const float* __restrict__ B,
    const float* __restrict__ bias, float* __restrict__ C,
    int M, int N, int K)
{
    __shared__ float As[BK][BM + 4];  // [k][m], transposed on load
    __shared__ float Bs[BK][BN];      // [k][n]

    const int tid = threadIdx.x;
    const int tx = tid & 15;
    const int ty = tid >> 4;
    const int bm = blockIdx.y * BM;
    const int bn = blockIdx.x * BN;

    float acc[8][8];
#pragma unroll
    for (int i = 0; i < 8; i++)
#pragma unroll
        for (int j = 0; j < 8; j++) acc[i][j] = 0.0f;

    for (int k0 = 0; k0 < K; k0 += BK) {
        // Load A tile 128x16 (512 float4s, 2 per thread), store transposed
#pragma unroll
        for (int t = 0; t < 2; t++) {
            int f   = tid + t * 256;
            int row = f >> 2;            // 4 float4 per row
            int kc  = (f & 3) << 2;
            float4 a = *(const float4*)(A + (size_t)(bm + row) * K + k0 + kc);
            As[kc + 0][row] = a.x;
            As[kc + 1][row] = a.y;
            As[kc + 2][row] = a.z;
            As[kc + 3][row] = a.w;
        }
        // Load B tile 16x128 (512 float4s, 2 per thread)
#pragma unroll
        for (int t = 0; t < 2; t++) {
            int f   = tid + t * 256;
            int row = f >> 5;            // 32 float4 per row
            int cc  = (f & 31) << 2;
            *(float4*)(&Bs[row][cc]) =
                *(const float4*)(B + (size_t)(k0 + row) * N + bn + cc);
        }
        __syncthreads();

#pragma unroll
        for (int k = 0; k < BK; k++) {
            float ar[8], br[8];
#pragma unroll
            for (int i = 0; i < 4; i++) {
                ar[i]     = As[k][ty * 4 + i];
                ar[4 + i] = As[k][64 + ty * 4 + i];
            }
#pragma unroll
            for (int j = 0; j < 4; j++) {
                br[j]     = Bs[k][tx * 4 + j];
                br[4 + j] = Bs[k][64 + tx * 4 + j];
            }
#pragma unroll
            for (int i = 0; i < 8; i++)
#pragma unroll
                for (int j = 0; j < 8; j++) acc[i][j] += ar[i] * br[j];
        }
        __syncthreads();
    }

    // Epilogue: add bias, vectorized stores
#pragma unroll
    for (int i = 0; i < 8; i++) {
        int row = bm + ((i < 4) ? (ty * 4 + i) : (64 + ty * 4 + (i - 4)));
#pragma unroll
        for (int jj = 0; jj < 2; jj++) {
            int col = bn + ((jj == 0) ? (tx * 4) : (64 + tx * 4));
            float4 o;
            o.x = acc[i][jj * 4 + 0] + bias[col + 0];
            o.y = acc[i][jj * 4 + 1] + bias[col + 1];
            o.z = acc[i][jj * 4 + 2] + bias[col + 2];
            o.w = acc[i][jj * 4 + 3] + bias[col + 3];
            *(float4*)(C + (size_t)row * N + col) = o;
        }
    }
}

// ---------------------------------------------------------------------------
// Flash attention (fp32, causal). One CTA = (batch b, head h, 64-row q tile).
// 256 threads = 16x16; each thread owns a 4x4 score microtile and a 4x4 of
// the 64-wide (HDIM) output accumulator. Online softmax, causal tiles skipped.
// qkv layout: [B, S, 3H] with q|k|v contiguous thirds; head h at offset h*64.
// ---------------------------------------------------------------------------
__global__ __launch_bounds__(256) void flash_attn(
    const float* __restrict__ qkv, float* __restrict__ ctx)
{
    extern __shared__ float sm[];
    float* Qs = sm;                 // [64][65]  (d-major: Qs[d*65 + r])
    float* Ks = Qs + 64 * 65;       // [64][65]  (d-major: Ks[d*65 + c])
    float* Ps = Ks + 64 * 65;       // [64][65]  (Ps[r*65 + j])
    float* Vs = Ps + 64 * 65;       // [64][68]  (Vs[j*68 + c]), 68 for f4 align

    const int bq = blockIdx.x;      // q tile, 0..31
    const int h  = blockIdx.y;
    const int b  = blockIdx.z;
    const int tid = threadIdx.x;
    const int tx = tid & 15;
    const int ty = tid >> 4;

    const size_t rs = 3 * HID;      // row stride of qkv
    const float* qb = qkv + (size_t)b * S_LEN * rs + h * HDIM;
    const float* kb = qb + HID;
    const float* vb = qb + 2 * HID;

    // Load Q tile (scaled by 1/sqrt(64)), transposed to [d][r]
    for (int t = tid; t < 64 * 16; t += 256) {
        int r = t >> 4;
        int d = (t & 15) << 2;
        float4 q4 = *(const float4*)(qb + (size_t)(bq * 64 + r) * rs + d);
        Qs[(d + 0) * 65 + r] = q4.x * 0.125f;
        Qs[(d + 1) * 65 + r] = q4.y * 0.125f;
        Qs[(d + 2) * 65 + r] = q4.z * 0.125f;
        Qs[(d + 3) * 65 + r] = q4.w * 0.125f;
    }

    float m[4], l[4], acc[4][4];
#pragma unroll
    for (int i = 0; i < 4; i++) {
        m[i] = -1e30f;
        l[i] = 0.0f;
#pragma unroll
        for (int c = 0; c < 4; c++) acc[i][c] = 0.0f;
    }

    for (int kt = 0; kt <= bq; kt++) {
        __syncthreads();  // previous iter done reading Ks/Vs/Ps; Q visible

        // Load K (transposed [d][c]) and V ([j][c]) tiles
        for (int t = tid; t < 64 * 16; t += 256) {
            int c = t >> 4;
            int d = (t & 15) << 2;
            float4 k4 = *(const float4*)(kb + (size_t)(kt * 64 + c) * rs + d);
            Ks[(d + 0) * 65 + c] = k4.x;
            Ks[(d + 1) * 65 + c] = k4.y;
            Ks[(d + 2) * 65 + c] = k4.z;
            Ks[(d + 3) * 65 + c] = k4.w;
            float4 v4 = *(const float4*)(vb + (size_t)(kt * 64 + c) * rs + d);
            *(float4*)(&Vs[c * 68 + d]) = v4;
        }
        __syncthreads();

        // Scores: s[i][j] = sum_d Q[r_i][d] * K[c_j][d]
        float s[4][4];
#pragma unroll
        for (int i = 0; i < 4; i++)
#pragma unroll
            for (int j = 0; j < 4; j++) s[i][j] = 0.0f;

#pragma unroll 4
        for (int d = 0; d < 64; d++) {
            float qf[4], kf[4];
#pragma unroll
            for (int i = 0; i < 4; i++) qf[i] = Qs[d * 65 + ty * 4 + i];
#pragma unroll
            for (int j = 0; j < 4; j++) kf[j] = Ks[d * 65 + tx * 4 + j];
#pragma unroll
            for (int i = 0; i < 4; i++)
#pragma unroll
                for (int j = 0; j < 4; j++) s[i][j] += qf[i] * kf[j];
        }

        // Causal mask inside the diagonal tile
        if (kt == bq) {
#pragma unroll
            for (int i = 0; i < 4; i++)
#pragma unroll
                for (int j = 0; j < 4; j++)
                    if (tx * 4 + j > ty * 4 + i) s[i][j] = -1e9f;
        }

        // Online softmax update (row = 16 lanes sharing ty; xor<=8 stays in group)
#pragma unroll
        for (int i = 0; i < 4; i++) {
            float rmax = fmaxf(fmaxf(s[i][0], s[i][1]), fmaxf(s[i][2], s[i][3]));
#pragma unroll
            for (int o = 8; o > 0; o >>= 1)
                rmax = fmaxf(rmax, __shfl_xor_sync(0xffffffffu, rmax, o));
            float mn = fmaxf(m[i], rmax);
            float sc = __expf(m[i] - mn);
            float rsum = 0.0f;
#pragma unroll
            for (int j = 0; j < 4; j++) {
                float p = __expf(s[i][j] - mn);
                s[i][j] = p;
                rsum += p;
            }
#pragma unroll
            for (int o = 8; o > 0; o >>= 1)
                rsum += __shfl_xor_sync(0xffffffffu, rsum, o);
            l[i] = l[i] * sc + rsum;
            m[i] = mn;
#pragma unroll
            for (int c = 0; c < 4; c++) acc[i][c] *= sc;
#pragma unroll
            for (int j = 0; j < 4; j++)
                Ps[(ty * 4 + i) * 65 + tx * 4 + j] = s[i][j];
        }
        __syncthreads();

        // acc += P @ V
#pragma unroll 4
        for (int j = 0; j < 64; j++) {
            float pf[4];
#pragma unroll
            for (int i = 0; i < 4; i++) pf[i] = Ps[(ty * 4 + i) * 65 + j];
            float4 v4 = *(const float4*)(&Vs[j * 68 + tx * 4]);
#pragma unroll
            for (int i = 0; i < 4; i++) {
                acc[i][0] += pf[i] * v4.x;
                acc[i][1] += pf[i] * v4.y;
                acc[i][2] += pf[i] * v4.z;
                acc[i][3] += pf[i] * v4.w;
            }
        }
    }

    // Write context: ctx[b, s, h*64 + c]
#pragma unroll
    for (int i = 0; i < 4; i++) {
        float inv_l = 1.0f / l[i];
        size_t row = (size_t)(b * S_LEN + bq * 64 + ty * 4 + i);
        float* dst = ctx + row * HID + h * HDIM + tx * 4;
        float4 o;
        o.x = acc[i][0] * inv_l;
        o.y = acc[i][1] * inv_l;
        o.z = acc[i][2] * inv_l;
        o.w = acc[i][3] * inv_l;
        *(float4*)dst = o;
    }
}

// ---------------------------------------------------------------------------
// Launch
// ---------------------------------------------------------------------------
extern "C" void kernel_launch(void* const* d_in, const int* in_sizes, int n_in,
                              void* d_out, int out_size)
{
    const float* hidden = (const float*)d_in[0];
    // d_in[1] = mask (unused: causal structure implemented directly)
    const float* W_qkv = (const float*)d_in[2];
    const float* b_qkv = (const float*)d_in[3];
    const float* W_out = (const float*)d_in[4];
    const float* b_out = (const float*)d_in[5];
    float* out = (float*)d_out;

    float *qkv_d, *ctx_d;
    cudaGetSymbolAddress((void**)&qkv_d, g_qkv);
    cudaGetSymbolAddress((void**)&ctx_d, g_ctx);

    // 1) QKV projection: [4096,1024] x [1024,3072]
    sgemm_bias<<<dim3((3 * HID) / BN, MROWS / BM), 256>>>(
        hidden, W_qkv, b_qkv, qkv_d, MROWS, 3 * HID, HID);

    // 2) Flash attention
    int smem = (3 * 64 * 65 + 64 * 68) * (int)sizeof(float);  // 67,328 B
    cudaFuncSetAttribute(flash_attn, cudaFuncAttributeMaxDynamicSharedMemorySize, smem);
    flash_attn<<<dim3(S_LEN / 64, NHEAD, BATCH), 256, smem>>>(qkv_d, ctx_d);

    // 3) Output projection: [4096,1024] x [1024,1024] -> d_out
    sgemm_bias<<<dim3(HID / BN, MROWS / BM), 256>>>(
        ctx_d, W_out, b_out, out, MROWS, HID, HID);
}

// round 5
// speedup vs baseline: 1.3551x; 1.3551x over previous
#include <cuda_runtime.h>
#include <cuda_bf16.h>
#include <cstdint>

#define S_LEN 2048
#define HID   1024
#define NHEAD 16
#define HDIM  64
#define BATCH 2
#define MROWS (BATCH * S_LEN)   // 4096
#define K3    (3 * HID)         // 3072 (split-tripled K)

// ---------------------------------------------------------------------------
// Scratch (__device__ globals; no allocation allowed)
// ---------------------------------------------------------------------------
__device__ float g_qkv[(size_t)MROWS * 3 * HID];           // [4096, 3072]
__device__ float g_ctx[(size_t)MROWS * HID];               // [4096, 1024]
__device__ __nv_bfloat16 g_A[(size_t)MROWS * K3];          // [4096, 3072] = [hi|lo|hi]
__device__ __nv_bfloat16 g_Bqkv[(size_t)(3 * HID) * K3];   // [3072, 3072] = [hi|hi|lo]
__device__ __nv_bfloat16 g_Bout[(size_t)HID * K3];         // [1024, 3072]

// ---------------------------------------------------------------------------
// Helpers
// ---------------------------------------------------------------------------
__device__ __forceinline__ uint32_t smem_u32(const void* p) {
    uint32_t a;
    asm("{ .reg .u64 t; cvta.to.shared.u64 t, %1; cvt.u32.u64 %0, t; }" : "=r"(a) : "l"(p));
    return a;
}
__device__ __forceinline__ void cpasync16(uint32_t s, const void* g) {
    asm volatile("cp.async.cg.shared.global [%0], [%1], 16;" :: "r"(s), "l"(g));
}
__device__ __forceinline__ void ldm_x4(uint32_t* r, uint32_t addr) {
    asm volatile("ldmatrix.sync.aligned.m8n8.x4.shared.b16 {%0,%1,%2,%3}, [%4];"
        : "=r"(r[0]), "=r"(r[1]), "=r"(r[2]), "=r"(r[3]) : "r"(addr));
}
__device__ __forceinline__ void mma16816(float* d, const uint32_t* a, uint32_t b0, uint32_t b1) {
    asm volatile("mma.sync.aligned.m16n8k16.row.col.f32.bf16.bf16.f32 "
        "{%0,%1,%2,%3}, {%4,%5,%6,%7}, {%8,%9}, {%0,%1,%2,%3};"
        : "+f"(d[0]), "+f"(d[1]), "+f"(d[2]), "+f"(d[3])
        : "r"(a[0]), "r"(a[1]), "r"(a[2]), "r"(a[3]), "r"(b0), "r"(b1));
}

// ---------------------------------------------------------------------------
// Split conversions (bf16x3 trick, K-concatenated layout)
// ---------------------------------------------------------------------------
// X [M,K] fp32 -> A [M,3K] bf16 = [hi | lo | hi]
__global__ __launch_bounds__(256) void split_A(
    const float* __restrict__ X, __nv_bfloat16* __restrict__ A, int K, int M)
{
    int i = blockIdx.x * 256 + threadIdx.x;       // over M*K/4 float4s
    if (i >= M * (K / 4)) return;
    int row = i / (K / 4);
    int c = (i % (K / 4)) * 4;
    float4 x = ((const float4*)X)[i];
    float xs[4] = {x.x, x.y, x.z, x.w};
    __nv_bfloat16 h[4], l[4];
#pragma unroll
    for (int q = 0; q < 4; q++) {
        h[q] = __float2bfloat16_rn(xs[q]);
        l[q] = __float2bfloat16_rn(xs[q] - __bfloat162float(h[q]));
    }
    __nv_bfloat16* base = A + (size_t)row * 3 * K + c;
    *(uint2*)(base)         = *(uint2*)h;
    *(uint2*)(base + K)     = *(uint2*)l;
    *(uint2*)(base + 2 * K) = *(uint2*)h;
}

// W [K,N] fp32 -> B [N,3K] bf16 = [hi | hi | lo]  (transposed to K-major)
__global__ __launch_bounds__(256) void split_W(
    const float* __restrict__ W, __nv_bfloat16* __restrict__ Bo, int N, int K)
{
    __shared__ float t[32][33];
    int tx = threadIdx.x, ty = threadIdx.y;
    int n0 = blockIdx.x * 32, k0 = blockIdx.y * 32;
#pragma unroll
    for (int j = 0; j < 4; j++)
        t[ty + 8 * j][tx] = W[(size_t)(k0 + ty + 8 * j) * N + n0 + tx];
    __syncthreads();
#pragma unroll
    for (int j = 0; j < 4; j++) {
        float x = t[tx][ty + 8 * j];               // W[k0+tx][n0+ty+8j]
        __nv_bfloat16 h = __float2bfloat16_rn(x);
        __nv_bfloat16 l = __float2bfloat16_rn(x - __bfloat162float(h));
        size_t o = (size_t)(n0 + ty + 8 * j) * 3 * K + k0 + tx;
        Bo[o]         = h;
        Bo[o + K]     = h;
        Bo[o + 2 * K] = l;
    }
}

// ---------------------------------------------------------------------------
// HMMA GEMM: C[M,N] = A[M,K3] * B[N,K3]^T + bias
// 128x128x32 tiles, 4-stage cp.async, 8 warps (4Mx2N), warp tile 32x64.
// ---------------------------------------------------------------------------
#define BM 128
#define BN 128
#define BK 32
#define NSTG 4
#define LDS 80                  // smem row stride in bytes (32 bf16 + pad)
#define ASZ (BM * LDS)          // 10240
#define BSZ (BN * LDS)          // 10240
#define STG (ASZ + BSZ)         // 20480
#define GEMM_SMEM (NSTG * STG)  // 81920

__global__ __launch_bounds__(256) void hmma_gemm_bias(
    const __nv_bfloat16* __restrict__ A, const __nv_bfloat16* __restrict__ B,
    const float* __restrict__ bias, float* __restrict__ C, int N)
{
    extern __shared__ char sm[];
    uint32_t sb = smem_u32(sm);
    const int tid = threadIdx.x;
    const int lane = tid & 31;
    const int wid = tid >> 5;
    const int bm = blockIdx.y * BM;
    const int bn = blockIdx.x * BN;
    const int wm = (wid & 3) * 32;    // warp M offset in tile
    const int wn = (wid >> 2) * 64;   // warp N offset in tile

    float acc[2][8][4];
#pragma unroll
    for (int mt = 0; mt < 2; mt++)
#pragma unroll
        for (int nb = 0; nb < 8; nb++)
#pragma unroll
            for (int q = 0; q < 4; q++) acc[mt][nb][q] = 0.0f;

#define LOAD_STAGE(stg, k0) do {                                               \
    uint32_t so_ = sb + (stg) * STG;                                           \
    _Pragma("unroll")                                                          \
    for (int i_ = 0; i_ < 2; i_++) {                                           \
        int c_ = tid + i_ * 256;                                               \
        int r_ = c_ >> 2, ch_ = c_ & 3;                                        \
        cpasync16(so_ + r_ * LDS + ch_ * 16,                                   \
                  A + (size_t)(bm + r_) * K3 + (k0) + ch_ * 8);                \
    }                                                                          \
    _Pragma("unroll")                                                          \
    for (int i_ = 0; i_ < 2; i_++) {                                           \
        int c_ = tid + i_ * 256;                                               \
        int r_ = c_ >> 2, ch_ = c_ & 3;                                        \
        cpasync16(so_ + ASZ + r_ * LDS + ch_ * 16,                             \
                  B + (size_t)(bn + r_) * K3 + (k0) + ch_ * 8);                \
    }                                                                          \
} while (0)

    // Prologue: fill 3 stages
#pragma unroll
    for (int s = 0; s < 3; s++) {
        LOAD_STAGE(s, s * BK);
        asm volatile("cp.async.commit_group;" ::: "memory");
    }

    const int NIT = K3 / BK;   // 96
    for (int it = 0; it < NIT; it++) {
        asm volatile("cp.async.wait_group 2;" ::: "memory");
        __syncthreads();
        if (it + 3 < NIT) LOAD_STAGE((it + 3) & 3, (it + 3) * BK);
        asm volatile("cp.async.commit_group;" ::: "memory");

        uint32_t sa = sb + (it & 3) * STG;
        uint32_t sB = sa + ASZ;
#pragma unroll
        for (int ks = 0; ks < 2; ks++) {
            uint32_t a[2][4], b[4][4];
#pragma unroll
            for (int mt = 0; mt < 2; mt++) {
                uint32_t addr = sa + (wm + mt * 16 + (lane & 15)) * LDS
                              + ks * 32 + ((lane >> 4) << 4);
                ldm_x4(a[mt], addr);
            }
#pragma unroll
            for (int nb = 0; nb < 4; nb++) {
                uint32_t addr = sB + (wn + nb * 16 + (lane & 7) + ((lane >> 4) << 3)) * LDS
                              + ks * 32 + (((lane >> 3) & 1) << 4);
                ldm_x4(b[nb], addr);
            }
#pragma unroll
            for (int mt = 0; mt < 2; mt++)
#pragma unroll
                for (int nb = 0; nb < 4; nb++) {
                    mma16816(acc[mt][nb * 2 + 0], a[mt], b[nb][0], b[nb][1]);
                    mma16816(acc[mt][nb * 2 + 1], a[mt], b[nb][2], b[nb][3]);
                }
        }
    }

    // Epilogue: registers -> global with bias
    const int g = lane >> 2;
    const int tg = lane & 3;
#pragma unroll
    for (int mt = 0; mt < 2; mt++) {
        int row0 = bm + wm + mt * 16 + g;
#pragma unroll
        for (int nb = 0; nb < 8; nb++) {
            int col = bn + wn + nb * 8 + tg * 2;
            float bx = bias[col], by = bias[col + 1];
            float2 o0 = {acc[mt][nb][0] + bx, acc[mt][nb][1] + by};
            float2 o1 = {acc[mt][nb][2] + bx, acc[mt][nb][3] + by};
            *(float2*)(C + (size_t)row0 * N + col) = o0;
            *(float2*)(C + (size_t)(row0 + 8) * N + col) = o1;
        }
    }
#undef LOAD_STAGE
}

// ---------------------------------------------------------------------------
// Flash attention (fp32, causal) — unchanged (passing, ~670us)
// ---------------------------------------------------------------------------
__global__ __launch_bounds__(256) void flash_attn(
    const float* __restrict__ qkv, float* __restrict__ ctx)
{
    extern __shared__ float smf[];
    float* Qs = smf;
    float* Ks = Qs + 64 * 65;
    float* Ps = Ks + 64 * 65;
    float* Vs = Ps + 64 * 65;

    const int bq = blockIdx.x;
    const int h  = blockIdx.y;
    const int b  = blockIdx.z;
    const int tid = threadIdx.x;
    const int tx = tid & 15;
    const int ty = tid >> 4;

    const size_t rs = 3 * HID;
    const float* qb = qkv + (size_t)b * S_LEN * rs + h * HDIM;
    const float* kb = qb + HID;
    const float* vb = qb + 2 * HID;

    for (int t = tid; t < 64 * 16; t += 256) {
        int r = t >> 4;
        int d = (t & 15) << 2;
        float4 q4 = *(const float4*)(qb + (size_t)(bq * 64 + r) * rs + d);
        Qs[(d + 0) * 65 + r] = q4.x * 0.125f;
        Qs[(d + 1) * 65 + r] = q4.y * 0.125f;
        Qs[(d + 2) * 65 + r] = q4.z * 0.125f;
        Qs[(d + 3) * 65 + r] = q4.w * 0.125f;
    }

    float m[4], l[4], acc[4][4];
#pragma unroll
    for (int i = 0; i < 4; i++) {
        m[i] = -1e30f;
        l[i] = 0.0f;
#pragma unroll
        for (int c = 0; c < 4; c++) acc[i][c] = 0.0f;
    }

    for (int kt = 0; kt <= bq; kt++) {
        __syncthreads();
        for (int t = tid; t < 64 * 16; t += 256) {
            int c = t >> 4;
            int d = (t & 15) << 2;
            float4 k4 = *(const float4*)(kb + (size_t)(kt * 64 + c) * rs + d);
            Ks[(d + 0) * 65 + c] = k4.x;
            Ks[(d + 1) * 65 + c] = k4.y;
            Ks[(d + 2) * 65 + c] = k4.z;
            Ks[(d + 3) * 65 + c] = k4.w;
            float4 v4 = *(const float4*)(vb + (size_t)(kt * 64 + c) * rs + d);
            *(float4*)(&Vs[c * 68 + d]) = v4;
        }
        __syncthreads();

        float s[4][4];
#pragma unroll
        for (int i = 0; i < 4; i++)
#pragma unroll
            for (int j = 0; j < 4; j++) s[i][j] = 0.0f;

#pragma unroll 4
        for (int d = 0; d < 64; d++) {
            float qf[4], kf[4];
#pragma unroll
            for (int i = 0; i < 4; i++) qf[i] = Qs[d * 65 + ty * 4 + i];
#pragma unroll
            for (int j = 0; j < 4; j++) kf[j] = Ks[d * 65 + tx * 4 + j];
#pragma unroll
            for (int i = 0; i < 4; i++)
#pragma unroll
                for (int j = 0; j < 4; j++) s[i][j] += qf[i] * kf[j];
        }

        if (kt == bq) {
#pragma unroll
            for (int i = 0; i < 4; i++)
#pragma unroll
                for (int j = 0; j < 4; j++)
                    if (tx * 4 + j > ty * 4 + i) s[i][j] = -1e9f;
        }

#pragma unroll
        for (int i = 0; i < 4; i++) {
            float rmax = fmaxf(fmaxf(s[i][0], s[i][1]), fmaxf(s[i][2], s[i][3]));
#pragma unroll
            for (int o = 8; o > 0; o >>= 1)
                rmax = fmaxf(rmax, __shfl_xor_sync(0xffffffffu, rmax, o));
            float mn = fmaxf(m[i], rmax);
            float sc = __expf(m[i] - mn);
            float rsum = 0.0f;
#pragma unroll
            for (int j = 0; j < 4; j++) {
                float p = __expf(s[i][j] - mn);
                s[i][j] = p;
                rsum += p;
            }
#pragma unroll
            for (int o = 8; o > 0; o >>= 1)
                rsum += __shfl_xor_sync(0xffffffffu, rsum, o);
            l[i] = l[i] * sc + rsum;
            m[i] = mn;
#pragma unroll
            for (int c = 0; c < 4; c++) acc[i][c] *= sc;
#pragma unroll
            for (int j = 0; j < 4; j++)
                Ps[(ty * 4 + i) * 65 + tx * 4 + j] = s[i][j];
        }
        __syncthreads();

#pragma unroll 4
        for (int j = 0; j < 64; j++) {
            float pf[4];
#pragma unroll
            for (int i = 0; i < 4; i++) pf[i] = Ps[(ty * 4 + i) * 65 + j];
            float4 v4 = *(const float4*)(&Vs[j * 68 + tx * 4]);
#pragma unroll
            for (int i = 0; i < 4; i++) {
                acc[i][0] += pf[i] * v4.x;
                acc[i][1] += pf[i] * v4.y;
                acc[i][2] += pf[i] * v4.z;
                acc[i][3] += pf[i] * v4.w;
            }
        }
    }

#pragma unroll
    for (int i = 0; i < 4; i++) {
        float inv_l = 1.0f / l[i];
        size_t row = (size_t)(b * S_LEN + bq * 64 + ty * 4 + i);
        float* dst = ctx + row * HID + h * HDIM + tx * 4;
        float4 o;
        o.x = acc[i][0] * inv_l;
        o.y = acc[i][1] * inv_l;
        o.z = acc[i][2] * inv_l;
        o.w = acc[i][3] * inv_l;
        *(float4*)dst = o;
    }
}

// ---------------------------------------------------------------------------
// Launch
// ---------------------------------------------------------------------------
extern "C" void kernel_launch(void* const* d_in, const int* in_sizes, int n_in,
                              void* d_out, int out_size)
{
    const float* hidden = (const float*)d_in[0];
    const float* W_qkv = (const float*)d_in[2];
    const float* b_qkv = (const float*)d_in[3];
    const float* W_out = (const float*)d_in[4];
    const float* b_out = (const float*)d_in[5];
    float* out = (float*)d_out;

    float *qkv_d, *ctx_d;
    __nv_bfloat16 *A_d, *Bq_d, *Bo_d;
    cudaGetSymbolAddress((void**)&qkv_d, g_qkv);
    cudaGetSymbolAddress((void**)&ctx_d, g_ctx);
    cudaGetSymbolAddress((void**)&A_d, g_A);
    cudaGetSymbolAddress((void**)&Bq_d, g_Bqkv);
    cudaGetSymbolAddress((void**)&Bo_d, g_Bout);

    cudaFuncSetAttribute(hmma_gemm_bias, cudaFuncAttributeMaxDynamicSharedMemorySize, GEMM_SMEM);
    int fa_smem = (3 * 64 * 65 + 64 * 68) * (int)sizeof(float);
    cudaFuncSetAttribute(flash_attn, cudaFuncAttributeMaxDynamicSharedMemorySize, fa_smem);

    // 1) Split inputs for QKV GEMM
    int n4 = MROWS * (HID / 4);
    split_A<<<(n4 + 255) / 256, 256>>>(hidden, A_d, HID, MROWS);
    split_W<<<dim3(3 * HID / 32, HID / 32), dim3(32, 8)>>>(W_qkv, Bq_d, 3 * HID, HID);

    // 2) QKV projection: [4096,3072(split)] x [3072,3072(split)]^T
    hmma_gemm_bias<<<dim3(3 * HID / BN, MROWS / BM), 256, GEMM_SMEM>>>(
        A_d, Bq_d, b_qkv, qkv_d, 3 * HID);

    // 3) Flash attention
    flash_attn<<<dim3(S_LEN / 64, NHEAD, BATCH), 256, fa_smem>>>(qkv_d, ctx_d);

    // 4) Split ctx + W_out
    split_A<<<(n4 + 255) / 256, 256>>>(ctx_d, A_d, HID, MROWS);
    split_W<<<dim3(HID / 32, HID / 32), dim3(32, 8)>>>(W_out, Bo_d, HID, HID);

    // 5) Output projection -> d_out
    hmma_gemm_bias<<<dim3(HID / BN, MROWS / BM), 256, GEMM_SMEM>>>(
        A_d, Bo_d, b_out, out, HID);
}

// round 6
// speedup vs baseline: 2.4585x; 1.8142x over previous
#include <cuda_runtime.h>
#include <cuda_bf16.h>
#include <cstdint>

#define S_LEN 2048
#define HID   1024
#define NHEAD 16
#define HDIM  64
#define BATCH 2
#define MROWS (BATCH * S_LEN)   // 4096
#define K3    (3 * HID)         // 3072 (split-tripled K)

// ---------------------------------------------------------------------------
// Scratch (__device__ globals; no allocation allowed)
// ---------------------------------------------------------------------------
__device__ float g_qkv[(size_t)MROWS * 3 * HID];           // [4096, 3072]
__device__ float g_ctx[(size_t)MROWS * HID];               // [4096, 1024]
__device__ __nv_bfloat16 g_A[(size_t)MROWS * K3];          // [4096, 3072] = [hi|lo|hi]
__device__ __nv_bfloat16 g_Bqkv[(size_t)(3 * HID) * K3];   // [3072, 3072] = [hi|hi|lo]
__device__ __nv_bfloat16 g_Bout[(size_t)HID * K3];         // [1024, 3072]

// ---------------------------------------------------------------------------
// Helpers
// ---------------------------------------------------------------------------
__device__ __forceinline__ uint32_t smem_u32(const void* p) {
    uint32_t a;
    asm("{ .reg .u64 t; cvta.to.shared.u64 t, %1; cvt.u32.u64 %0, t; }" : "=r"(a) : "l"(p));
    return a;
}
__device__ __forceinline__ void cpasync16(uint32_t s, const void* g) {
    asm volatile("cp.async.cg.shared.global [%0], [%1], 16;" :: "r"(s), "l"(g));
}
__device__ __forceinline__ void ldm_x4(uint32_t* r, uint32_t addr) {
    asm volatile("ldmatrix.sync.aligned.m8n8.x4.shared.b16 {%0,%1,%2,%3}, [%4];"
        : "=r"(r[0]), "=r"(r[1]), "=r"(r[2]), "=r"(r[3]) : "r"(addr));
}
__device__ __forceinline__ void ldm_x4_t(uint32_t* r, uint32_t addr) {
    asm volatile("ldmatrix.sync.aligned.m8n8.x4.trans.shared.b16 {%0,%1,%2,%3}, [%4];"
        : "=r"(r[0]), "=r"(r[1]), "=r"(r[2]), "=r"(r[3]) : "r"(addr));
}
__device__ __forceinline__ void mma16816(float* d, const uint32_t* a, uint32_t b0, uint32_t b1) {
    asm volatile("mma.sync.aligned.m16n8k16.row.col.f32.bf16.bf16.f32 "
        "{%0,%1,%2,%3}, {%4,%5,%6,%7}, {%8,%9}, {%0,%1,%2,%3};"
        : "+f"(d[0]), "+f"(d[1]), "+f"(d[2]), "+f"(d[3])
        : "r"(a[0]), "r"(a[1]), "r"(a[2]), "r"(a[3]), "r"(b0), "r"(b1));
}
__device__ __forceinline__ float ex2(float x) {
    float y; asm("ex2.approx.ftz.f32 %0, %1;" : "=f"(y) : "f"(x)); return y;
}
// pack two floats into bf16x2 (lo -> low half, hi -> high half)
__device__ __forceinline__ uint32_t packlh(float lo, float hi) {
    uint32_t d; asm("cvt.rn.bf16x2.f32 %0, %1, %2;" : "=r"(d) : "f"(hi), "f"(lo)); return d;
}

// ---------------------------------------------------------------------------
// Split conversions (bf16x3 trick, K-concatenated layout)
// ---------------------------------------------------------------------------
__global__ __launch_bounds__(256) void split_A(
    const float* __restrict__ X, __nv_bfloat16* __restrict__ A, int K, int M)
{
    int i = blockIdx.x * 256 + threadIdx.x;
    if (i >= M * (K / 4)) return;
    int row = i / (K / 4);
    int c = (i % (K / 4)) * 4;
    float4 x = ((const float4*)X)[i];
    float xs[4] = {x.x, x.y, x.z, x.w};
    __nv_bfloat16 h[4], l[4];
#pragma unroll
    for (int q = 0; q < 4; q++) {
        h[q] = __float2bfloat16_rn(xs[q]);
        l[q] = __float2bfloat16_rn(xs[q] - __bfloat162float(h[q]));
    }
    __nv_bfloat16* base = A + (size_t)row * 3 * K + c;
    *(uint2*)(base)         = *(uint2*)h;
    *(uint2*)(base + K)     = *(uint2*)l;
    *(uint2*)(base + 2 * K) = *(uint2*)h;
}

__global__ __launch_bounds__(256) void split_W(
    const float* __restrict__ W, __nv_bfloat16* __restrict__ Bo, int N, int K)
{
    __shared__ float t[32][33];
    int tx = threadIdx.x, ty = threadIdx.y;
    int n0 = blockIdx.x * 32, k0 = blockIdx.y * 32;
#pragma unroll
    for (int j = 0; j < 4; j++)
        t[ty + 8 * j][tx] = W[(size_t)(k0 + ty + 8 * j) * N + n0 + tx];
    __syncthreads();
#pragma unroll
    for (int j = 0; j < 4; j++) {
        float x = t[tx][ty + 8 * j];
        __nv_bfloat16 h = __float2bfloat16_rn(x);
        __nv_bfloat16 l = __float2bfloat16_rn(x - __bfloat162float(h));
        size_t o = (size_t)(n0 + ty + 8 * j) * 3 * K + k0 + tx;
        Bo[o]         = h;
        Bo[o + K]     = h;
        Bo[o + 2 * K] = l;
    }
}

// ---------------------------------------------------------------------------
// HMMA GEMM (unchanged, verified rel_err 2e-5)
// ---------------------------------------------------------------------------
#define BM 128
#define BN 128
#define BK 32
#define NSTG 4
#define LDS 80
#define ASZ (BM * LDS)
#define BSZ (BN * LDS)
#define STG (ASZ + BSZ)
#define GEMM_SMEM (NSTG * STG)

__global__ __launch_bounds__(256) void hmma_gemm_bias(
    const __nv_bfloat16* __restrict__ A, const __nv_bfloat16* __restrict__ B,
    const float* __restrict__ bias, float* __restrict__ C, int N)
{
    extern __shared__ char sm[];
    uint32_t sb = smem_u32(sm);
    const int tid = threadIdx.x;
    const int lane = tid & 31;
    const int wid = tid >> 5;
    const int bm = blockIdx.y * BM;
    const int bn = blockIdx.x * BN;
    const int wm = (wid & 3) * 32;
    const int wn = (wid >> 2) * 64;

    float acc[2][8][4];
#pragma unroll
    for (int mt = 0; mt < 2; mt++)
#pragma unroll
        for (int nb = 0; nb < 8; nb++)
#pragma unroll
            for (int q = 0; q < 4; q++) acc[mt][nb][q] = 0.0f;

#define LOAD_STAGE(stg, k0) do {                                               \
    uint32_t so_ = sb + (stg) * STG;                                           \
    _Pragma("unroll")                                                          \
    for (int i_ = 0; i_ < 2; i_++) {                                           \
        int c_ = tid + i_ * 256;                                               \
        int r_ = c_ >> 2, ch_ = c_ & 3;                                        \
        cpasync16(so_ + r_ * LDS + ch_ * 16,                                   \
                  A + (size_t)(bm + r_) * K3 + (k0) + ch_ * 8);                \
    }                                                                          \
    _Pragma("unroll")                                                          \
    for (int i_ = 0; i_ < 2; i_++) {                                           \
        int c_ = tid + i_ * 256;                                               \
        int r_ = c_ >> 2, ch_ = c_ & 3;                                        \
        cpasync16(so_ + ASZ + r_ * LDS + ch_ * 16,                             \
                  B + (size_t)(bn + r_) * K3 + (k0) + ch_ * 8);                \
    }                                                                          \
} while (0)

#pragma unroll
    for (int s = 0; s < 3; s++) {
        LOAD_STAGE(s, s * BK);
        asm volatile("cp.async.commit_group;" ::: "memory");
    }

    const int NIT = K3 / BK;
    for (int it = 0; it < NIT; it++) {
        asm volatile("cp.async.wait_group 2;" ::: "memory");
        __syncthreads();
        if (it + 3 < NIT) LOAD_STAGE((it + 3) & 3, (it + 3) * BK);
        asm volatile("cp.async.commit_group;" ::: "memory");

        uint32_t sa = sb + (it & 3) * STG;
        uint32_t sB = sa + ASZ;
#pragma unroll
        for (int ks = 0; ks < 2; ks++) {
            uint32_t a[2][4], b[4][4];
#pragma unroll
            for (int mt = 0; mt < 2; mt++) {
                uint32_t addr = sa + (wm + mt * 16 + (lane & 15)) * LDS
                              + ks * 32 + ((lane >> 4) << 4);
                ldm_x4(a[mt], addr);
            }
#pragma unroll
            for (int nb = 0; nb < 4; nb++) {
                uint32_t addr = sB + (wn + nb * 16 + (lane & 7) + ((lane >> 4) << 3)) * LDS
                              + ks * 32 + (((lane >> 3) & 1) << 4);
                ldm_x4(b[nb], addr);
            }
#pragma unroll
            for (int mt = 0; mt < 2; mt++)
#pragma unroll
                for (int nb = 0; nb < 4; nb++) {
                    mma16816(acc[mt][nb * 2 + 0], a[mt], b[nb][0], b[nb][1]);
                    mma16816(acc[mt][nb * 2 + 1], a[mt], b[nb][2], b[nb][3]);
                }
        }
    }

    const int g = lane >> 2;
    const int tg = lane & 3;
#pragma unroll
    for (int mt = 0; mt < 2; mt++) {
        int row0 = bm + wm + mt * 16 + g;
#pragma unroll
        for (int nb = 0; nb < 8; nb++) {
            int col = bn + wn + nb * 8 + tg * 2;
            float bx = bias[col], by = bias[col + 1];
            float2 o0 = {acc[mt][nb][0] + bx, acc[mt][nb][1] + by};
            float2 o1 = {acc[mt][nb][2] + bx, acc[mt][nb][3] + by};
            *(float2*)(C + (size_t)row0 * N + col) = o0;
            *(float2*)(C + (size_t)(row0 + 8) * N + col) = o1;
        }
    }
#undef LOAD_STAGE
}

// ---------------------------------------------------------------------------
// HMMA flash attention (causal), bf16 hi/lo splits for QK and PV.
// CTA = 128 q rows x (b,h). 8 warps x 16 rows. K-tiles of 64 keys.
// smem: Qs[128][hi64|lo64], Ks[64][hi64|lo64], Vs[64][hi64|lo64] (row=key,col=dim)
// row stride 272B (conflict-free for ldmatrix, 8-byte aligned).
// ---------------------------------------------------------------------------
#define FROW 272
#define QSM  0
#define KSM  (128 * FROW)           // 34816
#define VSM  (KSM + 64 * FROW)      // 52224
#define FA_SMEM (VSM + 64 * FROW)   // 69632

__global__ __launch_bounds__(256) void flash_attn_mma(
    const float* __restrict__ qkv, float* __restrict__ ctx)
{
    extern __shared__ char smem[];
    uint32_t sb = smem_u32(smem);
    const int Tq = (S_LEN / 128 - 1) - blockIdx.x;   // heavy tiles first
    const int h = blockIdx.y, b = blockIdx.z;
    const int tid = threadIdx.x, lane = tid & 31, w = tid >> 5;
    const int g = lane >> 2, tg = lane & 3;

    const float* qb_ = qkv + (size_t)b * S_LEN * 3072 + h * 64;
    const float* kb_ = qb_ + 1024;
    const float* vb_ = qb_ + 2048;

    // Load + split Q (fold 1/8 * log2e so softmax runs in base 2)
    const float QS = 0.125f * 1.44269504f;
#pragma unroll
    for (int i = 0; i < 8; i++) {
        int e = tid + i * 256, r = e >> 4, c4 = e & 15;
        float4 q = *(const float4*)(qb_ + (size_t)(Tq * 128 + r) * 3072 + c4 * 4);
        q.x *= QS; q.y *= QS; q.z *= QS; q.w *= QS;
        __nv_bfloat162 h01 = __floats2bfloat162_rn(q.x, q.y);
        __nv_bfloat162 h23 = __floats2bfloat162_rn(q.z, q.w);
        uint2 hi = {*(uint32_t*)&h01, *(uint32_t*)&h23};
        uint2 lo = {packlh(q.x - __low2float(h01), q.y - __high2float(h01)),
                    packlh(q.z - __low2float(h23), q.w - __high2float(h23))};
        *(uint2*)(smem + QSM + r * FROW + c4 * 8) = hi;
        *(uint2*)(smem + QSM + r * FROW + 128 + c4 * 8) = lo;
    }

    float m0 = -1e30f, m1 = -1e30f, l0 = 0.0f, l1 = 0.0f;
    float acc[8][4];
#pragma unroll
    for (int nb = 0; nb < 8; nb++)
#pragma unroll
        for (int q = 0; q < 4; q++) acc[nb][q] = 0.0f;

    const int KT = 2 * Tq + 2;
    float4 pk[4], pv[4];
#pragma unroll
    for (int i = 0; i < 4; i++) {
        int e = tid + i * 256, r = e >> 4, c4 = e & 15;
        pk[i] = *(const float4*)(kb_ + (size_t)r * 3072 + c4 * 4);
        pv[i] = *(const float4*)(vb_ + (size_t)r * 3072 + c4 * 4);
    }

    for (int kt = 0; kt < KT; kt++) {
        // store prefetched K/V tile (split hi/lo)
#pragma unroll
        for (int i = 0; i < 4; i++) {
            int e = tid + i * 256, r = e >> 4, c4 = e & 15;
            float4 x = pk[i];
            __nv_bfloat162 h01 = __floats2bfloat162_rn(x.x, x.y);
            __nv_bfloat162 h23 = __floats2bfloat162_rn(x.z, x.w);
            uint2 khi = {*(uint32_t*)&h01, *(uint32_t*)&h23};
            uint2 klo = {packlh(x.x - __low2float(h01), x.y - __high2float(h01)),
                         packlh(x.z - __low2float(h23), x.w - __high2float(h23))};
            *(uint2*)(smem + KSM + r * FROW + c4 * 8) = khi;
            *(uint2*)(smem + KSM + r * FROW + 128 + c4 * 8) = klo;
            x = pv[i];
            h01 = __floats2bfloat162_rn(x.x, x.y);
            h23 = __floats2bfloat162_rn(x.z, x.w);
            uint2 vhi = {*(uint32_t*)&h01, *(uint32_t*)&h23};
            uint2 vlo = {packlh(x.x - __low2float(h01), x.y - __high2float(h01)),
                         packlh(x.z - __low2float(h23), x.w - __high2float(h23))};
            *(uint2*)(smem + VSM + r * FROW + c4 * 8) = vhi;
            *(uint2*)(smem + VSM + r * FROW + 128 + c4 * 8) = vlo;
        }
        __syncthreads();
        if (kt + 1 < KT) {
#pragma unroll
            for (int i = 0; i < 4; i++) {
                int e = tid + i * 256, r = e >> 4, c4 = e & 15;
                pk[i] = *(const float4*)(kb_ + (size_t)((kt + 1) * 64 + r) * 3072 + c4 * 4);
                pv[i] = *(const float4*)(vb_ + (size_t)((kt + 1) * 64 + r) * 3072 + c4 * 4);
            }
        }

        const int wrow = Tq * 128 + w * 16;
        bool skip = (kt * 64 > wrow + 15);   // tile entirely above diagonal for this warp
        if (!skip) {
            // ---- scores S[16,64] = Q'.K'^T (3-pass split) ----
            float s[8][4];
#pragma unroll
            for (int nb = 0; nb < 8; nb++)
#pragma unroll
                for (int q = 0; q < 4; q++) s[nb][q] = 0.0f;

#pragma unroll
            for (int ks = 0; ks < 4; ks++) {
                uint32_t ah[4], al[4];
                uint32_t qaddr = sb + QSM + (w * 16 + (lane & 15)) * FROW
                               + ks * 32 + ((lane >> 4) << 4);
                ldm_x4(ah, qaddr);
                ldm_x4(al, qaddr + 128);
#pragma unroll
                for (int nb2 = 0; nb2 < 4; nb2++) {
                    uint32_t bk[4];
                    uint32_t kaddr = sb + KSM
                                   + (nb2 * 16 + (lane & 7) + ((lane >> 4) << 3)) * FROW
                                   + ks * 32 + (((lane >> 3) & 1) << 4);
                    ldm_x4(bk, kaddr);
                    mma16816(s[nb2 * 2],     ah, bk[0], bk[1]);
                    mma16816(s[nb2 * 2 + 1], ah, bk[2], bk[3]);
                    mma16816(s[nb2 * 2],     al, bk[0], bk[1]);
                    mma16816(s[nb2 * 2 + 1], al, bk[2], bk[3]);
                    ldm_x4(bk, kaddr + 128);
                    mma16816(s[nb2 * 2],     ah, bk[0], bk[1]);
                    mma16816(s[nb2 * 2 + 1], ah, bk[2], bk[3]);
                }
            }

            // ---- causal mask (diagonal tiles only) ----
            if (kt * 64 + 63 > wrow) {
                int r0g = wrow + g, r1g = r0g + 8;
#pragma unroll
                for (int nb = 0; nb < 8; nb++) {
                    int kc = kt * 64 + nb * 8 + tg * 2;
                    if (kc     > r0g) s[nb][0] = -1e30f;
                    if (kc + 1 > r0g) s[nb][1] = -1e30f;
                    if (kc     > r1g) s[nb][2] = -1e30f;
                    if (kc + 1 > r1g) s[nb][3] = -1e30f;
                }
            }

            // ---- online softmax (base 2), P -> bf16 hi/lo A-fragments ----
            float mx0 = -1e30f, mx1 = -1e30f;
#pragma unroll
            for (int nb = 0; nb < 8; nb++) {
                mx0 = fmaxf(mx0, fmaxf(s[nb][0], s[nb][1]));
                mx1 = fmaxf(mx1, fmaxf(s[nb][2], s[nb][3]));
            }
            mx0 = fmaxf(mx0, __shfl_xor_sync(0xffffffffu, mx0, 1));
            mx0 = fmaxf(mx0, __shfl_xor_sync(0xffffffffu, mx0, 2));
            mx1 = fmaxf(mx1, __shfl_xor_sync(0xffffffffu, mx1, 1));
            mx1 = fmaxf(mx1, __shfl_xor_sync(0xffffffffu, mx1, 2));
            float mn0 = fmaxf(m0, mx0), mn1 = fmaxf(m1, mx1);
            float sc0 = ex2(m0 - mn0), sc1 = ex2(m1 - mn1);
            float sum0 = 0.0f, sum1 = 0.0f;
            uint32_t aphi[4][4], aplo[4][4];
#pragma unroll
            for (int ks = 0; ks < 4; ks++)
#pragma unroll
                for (int hf = 0; hf < 2; hf++) {
                    int nb = ks * 2 + hf;
                    float p0 = ex2(s[nb][0] - mn0);
                    float p1 = ex2(s[nb][1] - mn0);
                    float p2 = ex2(s[nb][2] - mn1);
                    float p3 = ex2(s[nb][3] - mn1);
                    sum0 += p0 + p1; sum1 += p2 + p3;
                    __nv_bfloat162 t01 = __floats2bfloat162_rn(p0, p1);
                    __nv_bfloat162 t23 = __floats2bfloat162_rn(p2, p3);
                    aphi[ks][hf * 2]     = *(uint32_t*)&t01;
                    aphi[ks][hf * 2 + 1] = *(uint32_t*)&t23;
                    aplo[ks][hf * 2]     = packlh(p0 - __low2float(t01), p1 - __high2float(t01));
                    aplo[ks][hf * 2 + 1] = packlh(p2 - __low2float(t23), p3 - __high2float(t23));
                }
            sum0 += __shfl_xor_sync(0xffffffffu, sum0, 1);
            sum0 += __shfl_xor_sync(0xffffffffu, sum0, 2);
            sum1 += __shfl_xor_sync(0xffffffffu, sum1, 1);
            sum1 += __shfl_xor_sync(0xffffffffu, sum1, 2);
            l0 = l0 * sc0 + sum0; l1 = l1 * sc1 + sum1;
            m0 = mn0; m1 = mn1;
#pragma unroll
            for (int nb = 0; nb < 8; nb++) {
                acc[nb][0] *= sc0; acc[nb][1] *= sc0;
                acc[nb][2] *= sc1; acc[nb][3] *= sc1;
            }

            // ---- ctx += P.V (3-pass split; V as trans-ldmatrix B) ----
#pragma unroll
            for (int ks = 0; ks < 4; ks++) {
#pragma unroll
                for (int nb2 = 0; nb2 < 4; nb2++) {
                    uint32_t bv[4];
                    uint32_t vaddr = sb + VSM
                                   + (ks * 16 + ((lane >> 3) & 1) * 8 + (lane & 7)) * FROW
                                   + nb2 * 32 + ((lane >> 4) << 4);
                    ldm_x4_t(bv, vaddr);
                    mma16816(acc[nb2 * 2],     aphi[ks], bv[0], bv[1]);
                    mma16816(acc[nb2 * 2 + 1], aphi[ks], bv[2], bv[3]);
                    mma16816(acc[nb2 * 2],     aplo[ks], bv[0], bv[1]);
                    mma16816(acc[nb2 * 2 + 1], aplo[ks], bv[2], bv[3]);
                    ldm_x4_t(bv, vaddr + 128);
                    mma16816(acc[nb2 * 2],     aphi[ks], bv[0], bv[1]);
                    mma16816(acc[nb2 * 2 + 1], aphi[ks], bv[2], bv[3]);
                }
            }
        }
        __syncthreads();
    }

    // ---- write ctx ----
    float inv0 = 1.0f / l0, inv1 = 1.0f / l1;
    int row0 = b * S_LEN + Tq * 128 + w * 16 + g;
#pragma unroll
    for (int nb = 0; nb < 8; nb++) {
        int col = h * 64 + nb * 8 + tg * 2;
        float2 o0 = {acc[nb][0] * inv0, acc[nb][1] * inv0};
        float2 o1 = {acc[nb][2] * inv1, acc[nb][3] * inv1};
        *(float2*)(ctx + (size_t)row0 * HID + col) = o0;
        *(float2*)(ctx + (size_t)(row0 + 8) * HID + col) = o1;
    }
}

// ---------------------------------------------------------------------------
// Launch
// ---------------------------------------------------------------------------
extern "C" void kernel_launch(void* const* d_in, const int* in_sizes, int n_in,
                              void* d_out, int out_size)
{
    const float* hidden = (const float*)d_in[0];
    const float* W_qkv = (const float*)d_in[2];
    const float* b_qkv = (const float*)d_in[3];
    const float* W_out = (const float*)d_in[4];
    const float* b_out = (const float*)d_in[5];
    float* out = (float*)d_out;

    float *qkv_d, *ctx_d;
    __nv_bfloat16 *A_d, *Bq_d, *Bo_d;
    cudaGetSymbolAddress((void**)&qkv_d, g_qkv);
    cudaGetSymbolAddress((void**)&ctx_d, g_ctx);
    cudaGetSymbolAddress((void**)&A_d, g_A);
    cudaGetSymbolAddress((void**)&Bq_d, g_Bqkv);
    cudaGetSymbolAddress((void**)&Bo_d, g_Bout);

    cudaFuncSetAttribute(hmma_gemm_bias, cudaFuncAttributeMaxDynamicSharedMemorySize, GEMM_SMEM);
    cudaFuncSetAttribute(flash_attn_mma, cudaFuncAttributeMaxDynamicSharedMemorySize, FA_SMEM);

    // 1) Split inputs for QKV GEMM
    int n4 = MROWS * (HID / 4);
    split_A<<<(n4 + 255) / 256, 256>>>(hidden, A_d, HID, MROWS);
    split_W<<<dim3(3 * HID / 32, HID / 32), dim3(32, 8)>>>(W_qkv, Bq_d, 3 * HID, HID);

    // 2) QKV projection
    hmma_gemm_bias<<<dim3(3 * HID / BN, MROWS / BM), 256, GEMM_SMEM>>>(
        A_d, Bq_d, b_qkv, qkv_d, 3 * HID);

    // 3) Flash attention (HMMA)
    flash_attn_mma<<<dim3(S_LEN / 128, NHEAD, BATCH), 256, FA_SMEM>>>(qkv_d, ctx_d);

    // 4) Split ctx + W_out
    split_A<<<(n4 + 255) / 256, 256>>>(ctx_d, A_d, HID, MROWS);
    split_W<<<dim3(HID / 32, HID / 32), dim3(32, 8)>>>(W_out, Bo_d, HID, HID);

    // 5) Output projection -> d_out
    hmma_gemm_bias<<<dim3(HID / BN, MROWS / BM), 256, GEMM_SMEM>>>(
        A_d, Bo_d, b_out, out, HID);
}

// round 10
// speedup vs baseline: 2.5322x; 1.0300x over previous
#include <cuda_runtime.h>
#include <cuda_bf16.h>
#include <cstdint>

#define S_LEN 2048
#define HID   1024
#define NHEAD 16
#define HDIM  64
#define BATCH 2
#define MROWS (BATCH * S_LEN)   // 4096
#define K3    (3 * HID)         // 3072 (split-tripled K)

// ---------------------------------------------------------------------------
// Scratch (__device__ globals; no allocation allowed)
// ---------------------------------------------------------------------------
__device__ __nv_bfloat16 g_A[(size_t)MROWS * K3];          // [4096, 3072] = [hi|lo|hi]
__device__ __nv_bfloat16 g_Bqkv[(size_t)(3 * HID) * K3];   // [3072, 3072] = [hi|hi|lo]
__device__ __nv_bfloat16 g_Bout[(size_t)HID * K3];         // [1024, 3072]
// Pre-split attention operands: [B*NH, S, 128] rows = hi(64) | lo(64) bf16
__device__ __nv_bfloat16 g_Qsp[(size_t)BATCH * NHEAD * S_LEN * 128];
__device__ __nv_bfloat16 g_Ksp[(size_t)BATCH * NHEAD * S_LEN * 128];
__device__ __nv_bfloat16 g_Vsp[(size_t)BATCH * NHEAD * S_LEN * 128];

// ---------------------------------------------------------------------------
// Helpers
// ---------------------------------------------------------------------------
__device__ __forceinline__ uint32_t smem_u32(const void* p) {
    uint32_t a;
    asm("{ .reg .u64 t; cvta.to.shared.u64 t, %1; cvt.u32.u64 %0, t; }" : "=r"(a) : "l"(p));
    return a;
}
__device__ __forceinline__ void cpasync16(uint32_t s, const void* g) {
    asm volatile("cp.async.cg.shared.global [%0], [%1], 16;" :: "r"(s), "l"(g));
}
__device__ __forceinline__ void ldm_x4(uint32_t* r, uint32_t addr) {
    asm volatile("ldmatrix.sync.aligned.m8n8.x4.shared.b16 {%0,%1,%2,%3}, [%4];"
        : "=r"(r[0]), "=r"(r[1]), "=r"(r[2]), "=r"(r[3]) : "r"(addr));
}
__device__ __forceinline__ void ldm_x4_t(uint32_t* r, uint32_t addr) {
    asm volatile("ldmatrix.sync.aligned.m8n8.x4.trans.shared.b16 {%0,%1,%2,%3}, [%4];"
        : "=r"(r[0]), "=r"(r[1]), "=r"(r[2]), "=r"(r[3]) : "r"(addr));
}
__device__ __forceinline__ void mma16816(float* d, const uint32_t* a, uint32_t b0, uint32_t b1) {
    asm volatile("mma.sync.aligned.m16n8k16.row.col.f32.bf16.bf16.f32 "
        "{%0,%1,%2,%3}, {%4,%5,%6,%7}, {%8,%9}, {%0,%1,%2,%3};"
        : "+f"(d[0]), "+f"(d[1]), "+f"(d[2]), "+f"(d[3])
        : "r"(a[0]), "r"(a[1]), "r"(a[2]), "r"(a[3]), "r"(b0), "r"(b1));
}
__device__ __forceinline__ float ex2(float x) {
    float y; asm("ex2.approx.ftz.f32 %0, %1;" : "=f"(y) : "f"(x)); return y;
}
__device__ __forceinline__ uint32_t packlh(float lo, float hi) {
    uint32_t d; asm("cvt.rn.bf16x2.f32 %0, %1, %2;" : "=r"(d) : "f"(hi), "f"(lo)); return d;
}

#define QSCALE (0.125f * 1.44269504f)

// ---------------------------------------------------------------------------
// Split conversions
// ---------------------------------------------------------------------------
__global__ __launch_bounds__(256) void split_A(
    const float* __restrict__ X, __nv_bfloat16* __restrict__ A, int K, int M)
{
    int i = blockIdx.x * 256 + threadIdx.x;
    if (i >= M * (K / 4)) return;
    int row = i / (K / 4);
    int c = (i % (K / 4)) * 4;
    float4 x = ((const float4*)X)[i];
    float xs[4] = {x.x, x.y, x.z, x.w};
    __nv_bfloat16 h[4], l[4];
#pragma unroll
    for (int q = 0; q < 4; q++) {
        h[q] = __float2bfloat16_rn(xs[q]);
        l[q] = __float2bfloat16_rn(xs[q] - __bfloat162float(h[q]));
    }
    __nv_bfloat16* base = A + (size_t)row * 3 * K + c;
    *(uint2*)(base)         = *(uint2*)h;
    *(uint2*)(base + K)     = *(uint2*)l;
    *(uint2*)(base + 2 * K) = *(uint2*)h;
}

__global__ __launch_bounds__(256) void split_W(
    const float* __restrict__ W, __nv_bfloat16* __restrict__ Bo, int N, int K)
{
    __shared__ float t[32][33];
    int tx = threadIdx.x, ty = threadIdx.y;
    int n0 = blockIdx.x * 32, k0 = blockIdx.y * 32;
#pragma unroll
    for (int j = 0; j < 4; j++)
        t[ty + 8 * j][tx] = W[(size_t)(k0 + ty + 8 * j) * N + n0 + tx];
    __syncthreads();
#pragma unroll
    for (int j = 0; j < 4; j++) {
        float x = t[tx][ty + 8 * j];
        __nv_bfloat16 h = __float2bfloat16_rn(x);
        __nv_bfloat16 l = __float2bfloat16_rn(x - __bfloat162float(h));
        size_t o = (size_t)(n0 + ty + 8 * j) * 3 * K + k0 + tx;
        Bo[o]         = h;
        Bo[o + K]     = h;
        Bo[o + 2 * K] = l;
    }
}

// ---------------------------------------------------------------------------
// HMMA GEMM core, templated epilogue:
//   QKV_EPI=0: C = fp32 (A.B^T + bias)    (out projection -> d_out)
//   QKV_EPI=1: writes bf16 hi/lo pre-split, head-major Qsp/Ksp/Vsp, Q scaled
// ---------------------------------------------------------------------------
#define BM 128
#define BN 128
#define BK 32
#define NSTG 4
#define LDS 80
#define ASZ (BM * LDS)
#define BSZ (BN * LDS)
#define STG (ASZ + BSZ)
#define GEMM_SMEM (NSTG * STG)

template <int QKV_EPI>
__global__ __launch_bounds__(256, 2) void hmma_gemm(
    const __nv_bfloat16* __restrict__ A, const __nv_bfloat16* __restrict__ B,
    const float* __restrict__ bias, float* __restrict__ C,
    __nv_bfloat16* __restrict__ Qsp, __nv_bfloat16* __restrict__ Ksp,
    __nv_bfloat16* __restrict__ Vsp, int N)
{
    extern __shared__ char sm[];
    uint32_t sb = smem_u32(sm);
    const int tid = threadIdx.x;
    const int lane = tid & 31;
    const int wid = tid >> 5;
    const int bm = blockIdx.y * BM;
    const int bn = blockIdx.x * BN;
    const int wm = (wid & 3) * 32;
    const int wn = (wid >> 2) * 64;

    float acc[2][8][4];
#pragma unroll
    for (int mt = 0; mt < 2; mt++)
#pragma unroll
        for (int nb = 0; nb < 8; nb++)
#pragma unroll
            for (int q = 0; q < 4; q++) acc[mt][nb][q] = 0.0f;

#define LOAD_STAGE(stg, k0) do {                                               \
    uint32_t so_ = sb + (stg) * STG;                                           \
    _Pragma("unroll")                                                          \
    for (int i_ = 0; i_ < 2; i_++) {                                           \
        int c_ = tid + i_ * 256;                                               \
        int r_ = c_ >> 2, ch_ = c_ & 3;                                        \
        cpasync16(so_ + r_ * LDS + ch_ * 16,                                   \
                  A + (size_t)(bm + r_) * K3 + (k0) + ch_ * 8);                \
    }                                                                          \
    _Pragma("unroll")                                                          \
    for (int i_ = 0; i_ < 2; i_++) {                                           \
        int c_ = tid + i_ * 256;                                               \
        int r_ = c_ >> 2, ch_ = c_ & 3;                                        \
        cpasync16(so_ + ASZ + r_ * LDS + ch_ * 16,                             \
                  B + (size_t)(bn + r_) * K3 + (k0) + ch_ * 8);                \
    }                                                                          \
} while (0)

#pragma unroll
    for (int s = 0; s < 3; s++) {
        LOAD_STAGE(s, s * BK);
        asm volatile("cp.async.commit_group;" ::: "memory");
    }

    const int NIT = K3 / BK;
    for (int it = 0; it < NIT; it++) {
        asm volatile("cp.async.wait_group 2;" ::: "memory");
        __syncthreads();
        if (it + 3 < NIT) LOAD_STAGE((it + 3) & 3, (it + 3) * BK);
        asm volatile("cp.async.commit_group;" ::: "memory");

        uint32_t sa = sb + (it & 3) * STG;
        uint32_t sB = sa + ASZ;
#pragma unroll
        for (int ks = 0; ks < 2; ks++) {
            uint32_t a[2][4], b[4][4];
#pragma unroll
            for (int mt = 0; mt < 2; mt++) {
                uint32_t addr = sa + (wm + mt * 16 + (lane & 15)) * LDS
                              + ks * 32 + ((lane >> 4) << 4);
                ldm_x4(a[mt], addr);
            }
#pragma unroll
            for (int nb = 0; nb < 4; nb++) {
                uint32_t addr = sB + (wn + nb * 16 + (lane & 7) + ((lane >> 4) << 3)) * LDS
                              + ks * 32 + (((lane >> 3) & 1) << 4);
                ldm_x4(b[nb], addr);
            }
#pragma unroll
            for (int mt = 0; mt < 2; mt++)
#pragma unroll
                for (int nb = 0; nb < 4; nb++) {
                    mma16816(acc[mt][nb * 2 + 0], a[mt], b[nb][0], b[nb][1]);
                    mma16816(acc[mt][nb * 2 + 1], a[mt], b[nb][2], b[nb][3]);
                }
        }
    }

    const int g = lane >> 2;
    const int tg = lane & 3;
#pragma unroll
    for (int mt = 0; mt < 2; mt++) {
        int row0 = bm + wm + mt * 16 + g;
#pragma unroll
        for (int nb = 0; nb < 8; nb++) {
            int col = bn + wn + nb * 8 + tg * 2;
            float bx = bias[col], by = bias[col + 1];
            float v00 = acc[mt][nb][0] + bx, v01 = acc[mt][nb][1] + by;
            float v10 = acc[mt][nb][2] + bx, v11 = acc[mt][nb][3] + by;
            if (QKV_EPI == 0) {
                float2 o0 = {v00, v01}, o1 = {v10, v11};
                *(float2*)(C + (size_t)row0 * N + col) = o0;
                *(float2*)(C + (size_t)(row0 + 8) * N + col) = o1;
            } else {
                int third = col >> 10;
                int head = (col >> 6) & 15;
                int dim = col & 63;
                __nv_bfloat16* base = (third == 0) ? Qsp : (third == 1) ? Ksp : Vsp;
                if (third == 0) { v00 *= QSCALE; v01 *= QSCALE; v10 *= QSCALE; v11 *= QSCALE; }
#pragma unroll
                for (int rr = 0; rr < 2; rr++) {
                    int m = row0 + rr * 8;
                    float va = rr ? v10 : v00, vb = rr ? v11 : v01;
                    int b_ = m >> 11, s_ = m & 2047;
                    size_t off = ((size_t)((b_ * NHEAD + head) * S_LEN + s_) << 7) + dim;
                    __nv_bfloat162 h2 = __floats2bfloat162_rn(va, vb);
                    uint32_t lo2 = packlh(va - __low2float(h2), vb - __high2float(h2));
                    *(uint32_t*)(base + off) = *(uint32_t*)&h2;
                    *(uint32_t*)(base + off + 64) = lo2;
                }
            }
        }
    }
#undef LOAD_STAGE
}

// ---------------------------------------------------------------------------
// HMMA flash attention (causal): cp.async 3-stage pipeline on pre-split bf16.
// CTA = 128 q rows x (b,h); 8 warps x 16 rows; 64-key tiles.
// smem rows: 272B stride; row = hi64 (128B) | lo64 (128B).
// Layout: Q[128 rows] | stage0 (K 64 rows, V 64 rows) | stage1 | stage2
// ---------------------------------------------------------------------------
#define FROW 272
#define QBYTES   (128 * FROW)           // 34816
#define KVSTAGE  (128 * FROW)           // K(64)+V(64) rows = 34816
#define VOFF     (64 * FROW)            // V offset inside stage
#define FA_SMEM  (QBYTES + 3 * KVSTAGE) // 139264

__global__ __launch_bounds__(256) void flash_attn_mma(
    const __nv_bfloat16* __restrict__ Qsp, const __nv_bfloat16* __restrict__ Ksp,
    const __nv_bfloat16* __restrict__ Vsp, __nv_bfloat16* __restrict__ Actx)
{
    extern __shared__ char smem[];
    uint32_t sb = smem_u32(smem);
    const int Tq = (S_LEN / 128 - 1) - blockIdx.x;   // heavy tiles first
    const int h = blockIdx.y, b = blockIdx.z;
    const int tid = threadIdx.x, lane = tid & 31, w = tid >> 5;
    const int g = lane >> 2, tg = lane & 3;
    const size_t bh = (size_t)(b * NHEAD + h) * S_LEN;
    const int KT = 2 * Tq + 2;

    // Prologue: Q tile + KV stage 0 (group 0), stages 1,2 (groups 1,2; may be empty)
#pragma unroll
    for (int i = 0; i < 8; i++) {
        int e = tid + i * 256, r = e >> 4, c = e & 15;
        cpasync16(sb + r * FROW + c * 16,
                  Qsp + ((bh + Tq * 128 + r) << 7) + c * 8);
    }
#define LOAD_KV(slot, t) do {                                                  \
    uint32_t st_ = sb + QBYTES + (slot) * KVSTAGE;                             \
    _Pragma("unroll")                                                          \
    for (int i_ = 0; i_ < 4; i_++) {                                           \
        int e_ = tid + i_ * 256;                                               \
        int r_ = e_ >> 4, c_ = e_ & 15;                                        \
        size_t src_ = ((bh + (t) * 64 + r_) << 7) + c_ * 8;                    \
        cpasync16(st_ + r_ * FROW + c_ * 16, Ksp + src_);                      \
        cpasync16(st_ + VOFF + r_ * FROW + c_ * 16, Vsp + src_);               \
    }                                                                          \
} while (0)
    LOAD_KV(0, 0);
    asm volatile("cp.async.commit_group;" ::: "memory");
    if (1 < KT) LOAD_KV(1, 1);
    asm volatile("cp.async.commit_group;" ::: "memory");
    if (2 < KT) LOAD_KV(2, 2);
    asm volatile("cp.async.commit_group;" ::: "memory");

    float m0 = -1e30f, m1 = -1e30f, l0 = 0.0f, l1 = 0.0f;
    float acc[8][4];
#pragma unroll
    for (int nb = 0; nb < 8; nb++)
#pragma unroll
        for (int q = 0; q < 4; q++) acc[nb][q] = 0.0f;

    int slot = 0;
    for (int kt = 0; kt < KT; kt++) {
        asm volatile("cp.async.wait_group 2;" ::: "memory");
        __syncthreads();

        const uint32_t stK = sb + QBYTES + slot * KVSTAGE;
        const uint32_t stV = stK + VOFF;
        const int wrow = Tq * 128 + w * 16;
        const bool skip = (kt * 64 > wrow + 15);

        if (!skip) {
            // ---- S[16,64] = Q.K^T (3-pass hi/lo) ----
            float s[8][4];
#pragma unroll
            for (int nb = 0; nb < 8; nb++)
#pragma unroll
                for (int q = 0; q < 4; q++) s[nb][q] = 0.0f;

#pragma unroll
            for (int ks = 0; ks < 4; ks++) {
                uint32_t ah[4], al[4];
                uint32_t qaddr = sb + (w * 16 + (lane & 15)) * FROW
                               + ks * 32 + ((lane >> 4) << 4);
                ldm_x4(ah, qaddr);
                ldm_x4(al, qaddr + 128);
#pragma unroll
                for (int nb2 = 0; nb2 < 4; nb2++) {
                    uint32_t bk[4];
                    uint32_t kaddr = stK
                                   + (nb2 * 16 + (lane & 7) + ((lane >> 4) << 3)) * FROW
                                   + ks * 32 + (((lane >> 3) & 1) << 4);
                    ldm_x4(bk, kaddr);
                    mma16816(s[nb2 * 2],     ah, bk[0], bk[1]);
                    mma16816(s[nb2 * 2 + 1], ah, bk[2], bk[3]);
                    mma16816(s[nb2 * 2],     al, bk[0], bk[1]);
                    mma16816(s[nb2 * 2 + 1], al, bk[2], bk[3]);
                    ldm_x4(bk, kaddr + 128);
                    mma16816(s[nb2 * 2],     ah, bk[0], bk[1]);
                    mma16816(s[nb2 * 2 + 1], ah, bk[2], bk[3]);
                }
            }

            // ---- causal mask (diagonal tiles) ----
            if (kt * 64 + 63 > wrow) {
                int r0g = wrow + g, r1g = r0g + 8;
#pragma unroll
                for (int nb = 0; nb < 8; nb++) {
                    int kc = kt * 64 + nb * 8 + tg * 2;
                    if (kc     > r0g) s[nb][0] = -1e30f;
                    if (kc + 1 > r0g) s[nb][1] = -1e30f;
                    if (kc     > r1g) s[nb][2] = -1e30f;
                    if (kc + 1 > r1g) s[nb][3] = -1e30f;
                }
            }

            // ---- online softmax (base 2), P -> bf16 hi/lo A-fragments ----
            float mx0 = -1e30f, mx1 = -1e30f;
#pragma unroll
            for (int nb = 0; nb < 8; nb++) {
                mx0 = fmaxf(mx0, fmaxf(s[nb][0], s[nb][1]));
                mx1 = fmaxf(mx1, fmaxf(s[nb][2], s[nb][3]));
            }
            mx0 = fmaxf(mx0, __shfl_xor_sync(0xffffffffu, mx0, 1));
            mx0 = fmaxf(mx0, __shfl_xor_sync(0xffffffffu, mx0, 2));
            mx1 = fmaxf(mx1, __shfl_xor_sync(0xffffffffu, mx1, 1));
            mx1 = fmaxf(mx1, __shfl_xor_sync(0xffffffffu, mx1, 2));
            float mn0 = fmaxf(m0, mx0), mn1 = fmaxf(m1, mx1);
            float sc0 = ex2(m0 - mn0), sc1 = ex2(m1 - mn1);
            float sum0 = 0.0f, sum1 = 0.0f;
            uint32_t aphi[4][4], aplo[4][4];
#pragma unroll
            for (int ks = 0; ks < 4; ks++)
#pragma unroll
                for (int hf = 0; hf < 2; hf++) {
                    int nb = ks * 2 + hf;
                    float p0 = ex2(s[nb][0] - mn0);
                    float p1 = ex2(s[nb][1] - mn0);
                    float p2 = ex2(s[nb][2] - mn1);
                    float p3 = ex2(s[nb][3] - mn1);
                    sum0 += p0 + p1; sum1 += p2 + p3;
                    __nv_bfloat162 t01 = __floats2bfloat162_rn(p0, p1);
                    __nv_bfloat162 t23 = __floats2bfloat162_rn(p2, p3);
                    aphi[ks][hf * 2]     = *(uint32_t*)&t01;
                    aphi[ks][hf * 2 + 1] = *(uint32_t*)&t23;
                    aplo[ks][hf * 2]     = packlh(p0 - __low2float(t01), p1 - __high2float(t01));
                    aplo[ks][hf * 2 + 1] = packlh(p2 - __low2float(t23), p3 - __high2float(t23));
                }
            sum0 += __shfl_xor_sync(0xffffffffu, sum0, 1);
            sum0 += __shfl_xor_sync(0xffffffffu, sum0, 2);
            sum1 += __shfl_xor_sync(0xffffffffu, sum1, 1);
            sum1 += __shfl_xor_sync(0xffffffffu, sum1, 2);
            l0 = l0 * sc0 + sum0; l1 = l1 * sc1 + sum1;
            m0 = mn0; m1 = mn1;
#pragma unroll
            for (int nb = 0; nb < 8; nb++) {
                acc[nb][0] *= sc0; acc[nb][1] *= sc0;
                acc[nb][2] *= sc1; acc[nb][3] *= sc1;
            }

            // ---- ctx += P.V (3-pass hi/lo; V via trans-ldmatrix) ----
#pragma unroll
            for (int ks = 0; ks < 4; ks++) {
#pragma unroll
                for (int nb2 = 0; nb2 < 4; nb2++) {
                    uint32_t bv[4];
                    uint32_t vaddr = stV
                                   + (ks * 16 + ((lane >> 3) & 1) * 8 + (lane & 7)) * FROW
                                   + nb2 * 32 + ((lane >> 4) << 4);
                    ldm_x4_t(bv, vaddr);
                    mma16816(acc[nb2 * 2],     aphi[ks], bv[0], bv[1]);
                    mma16816(acc[nb2 * 2 + 1], aphi[ks], bv[2], bv[3]);
                    mma16816(acc[nb2 * 2],     aplo[ks], bv[0], bv[1]);
                    mma16816(acc[nb2 * 2 + 1], aplo[ks], bv[2], bv[3]);
                    ldm_x4_t(bv, vaddr + 128);
                    mma16816(acc[nb2 * 2],     aphi[ks], bv[0], bv[1]);
                    mma16816(acc[nb2 * 2 + 1], aphi[ks], bv[2], bv[3]);
                }
            }
        }

        __syncthreads();   // all warps done reading slot before refill
        if (kt + 3 < KT) LOAD_KV(slot, kt + 3);
        asm volatile("cp.async.commit_group;" ::: "memory");
        slot = (slot == 2) ? 0 : slot + 1;
    }

    // ---- write ctx directly in g_A split layout [row, hi|lo|hi] ----
    float inv0 = 1.0f / l0, inv1 = 1.0f / l1;
    int row0 = b * S_LEN + Tq * 128 + w * 16 + g;
#pragma unroll
    for (int nb = 0; nb < 8; nb++) {
        int col = h * 64 + nb * 8 + tg * 2;
#pragma unroll
        for (int rr = 0; rr < 2; rr++) {
            float va = (rr ? acc[nb][2] * inv1 : acc[nb][0] * inv0);
            float vb = (rr ? acc[nb][3] * inv1 : acc[nb][1] * inv0);
            __nv_bfloat16* base = Actx + (size_t)(row0 + rr * 8) * K3 + col;
            __nv_bfloat162 h2 = __floats2bfloat162_rn(va, vb);
            uint32_t lo2 = packlh(va - __low2float(h2), vb - __high2float(h2));
            *(uint32_t*)(base)        = *(uint32_t*)&h2;
            *(uint32_t*)(base + 1024) = lo2;
            *(uint32_t*)(base + 2048) = *(uint32_t*)&h2;
        }
    }
}

// ---------------------------------------------------------------------------
// Launch
// ---------------------------------------------------------------------------
extern "C" void kernel_launch(void* const* d_in, const int* in_sizes, int n_in,
                              void* d_out, int out_size)
{
    const float* hidden = (const float*)d_in[0];
    const float* W_qkv = (const float*)d_in[2];
    const float* b_qkv = (const float*)d_in[3];
    const float* W_out = (const float*)d_in[4];
    const float* b_out = (const float*)d_in[5];
    float* out = (float*)d_out;

    __nv_bfloat16 *A_d, *Bq_d, *Bo_d, *Qsp, *Ksp, *Vsp;
    cudaGetSymbolAddress((void**)&A_d, g_A);
    cudaGetSymbolAddress((void**)&Bq_d, g_Bqkv);
    cudaGetSymbolAddress((void**)&Bo_d, g_Bout);
    cudaGetSymbolAddress((void**)&Qsp, g_Qsp);
    cudaGetSymbolAddress((void**)&Ksp, g_Ksp);
    cudaGetSymbolAddress((void**)&Vsp, g_Vsp);

    cudaFuncSetAttribute(hmma_gemm<0>, cudaFuncAttributeMaxDynamicSharedMemorySize, GEMM_SMEM);
    cudaFuncSetAttribute(hmma_gemm<1>, cudaFuncAttributeMaxDynamicSharedMemorySize, GEMM_SMEM);
    cudaFuncSetAttribute(flash_attn_mma, cudaFuncAttributeMaxDynamicSharedMemorySize, FA_SMEM);

    // 1) Split inputs
    int n4 = MROWS * (HID / 4);
    split_A<<<(n4 + 255) / 256, 256>>>(hidden, A_d, HID, MROWS);
    split_W<<<dim3(3 * HID / 32, HID / 32), dim3(32, 8)>>>(W_qkv, Bq_d, 3 * HID, HID);
    split_W<<<dim3(HID / 32, HID / 32), dim3(32, 8)>>>(W_out, Bo_d, HID, HID);

    // 2) QKV projection -> pre-split head-major Qsp/Ksp/Vsp (Q scaled)
    hmma_gemm<1><<<dim3(3 * HID / BN, MROWS / BM), 256, GEMM_SMEM>>>(
        A_d, Bq_d, b_qkv, nullptr, Qsp, Ksp, Vsp, 3 * HID);

    // 3) Flash attention -> ctx directly in g_A split layout
    flash_attn_mma<<<dim3(S_LEN / 128, NHEAD, BATCH), 256, FA_SMEM>>>(
        Qsp, Ksp, Vsp, A_d);

    // 4) Output projection -> d_out
    hmma_gemm<0><<<dim3(HID / BN, MROWS / BM), 256, GEMM_SMEM>>>(
        A_d, Bo_d, b_out, out, nullptr, nullptr, nullptr, HID);
}

// round 12
// speedup vs baseline: 2.7763x; 1.0964x over previous
#include <cuda_runtime.h>
#include <cuda_bf16.h>
#include <cstdint>

#define S_LEN 2048
#define HID   1024
#define NHEAD 16
#define HDIM  64
#define BATCH 2
#define MROWS (BATCH * S_LEN)   // 4096
#define K2    (2 * HID)         // 2048 (hi|lo split layout)

// ---------------------------------------------------------------------------
// Scratch (__device__ globals; no allocation allowed)
// ---------------------------------------------------------------------------
__device__ __nv_bfloat16 g_A[(size_t)MROWS * K2];          // [4096, 2048] = [hi|lo]
__device__ __nv_bfloat16 g_Bqkv[(size_t)(3 * HID) * K2];   // [3072, 2048] = [hi|lo]
__device__ __nv_bfloat16 g_Bout[(size_t)HID * K2];         // [1024, 2048]
// Pre-split attention operands: [B*NH, S, 128] rows = hi(64) | lo(64) bf16
__device__ __nv_bfloat16 g_Qsp[(size_t)BATCH * NHEAD * S_LEN * 128];
__device__ __nv_bfloat16 g_Ksp[(size_t)BATCH * NHEAD * S_LEN * 128];
__device__ __nv_bfloat16 g_Vsp[(size_t)BATCH * NHEAD * S_LEN * 128];

// ---------------------------------------------------------------------------
// Helpers
// ---------------------------------------------------------------------------
__device__ __forceinline__ uint32_t smem_u32(const void* p) {
    uint32_t a;
    asm("{ .reg .u64 t; cvta.to.shared.u64 t, %1; cvt.u32.u64 %0, t; }" : "=r"(a) : "l"(p));
    return a;
}
__device__ __forceinline__ void cpasync16(uint32_t s, const void* g) {
    asm volatile("cp.async.cg.shared.global [%0], [%1], 16;" :: "r"(s), "l"(g));
}
__device__ __forceinline__ void ldm_x4(uint32_t* r, uint32_t addr) {
    asm volatile("ldmatrix.sync.aligned.m8n8.x4.shared.b16 {%0,%1,%2,%3}, [%4];"
        : "=r"(r[0]), "=r"(r[1]), "=r"(r[2]), "=r"(r[3]) : "r"(addr));
}
__device__ __forceinline__ void ldm_x4_t(uint32_t* r, uint32_t addr) {
    asm volatile("ldmatrix.sync.aligned.m8n8.x4.trans.shared.b16 {%0,%1,%2,%3}, [%4];"
        : "=r"(r[0]), "=r"(r[1]), "=r"(r[2]), "=r"(r[3]) : "r"(addr));
}
__device__ __forceinline__ void mma16816(float* d, const uint32_t* a, uint32_t b0, uint32_t b1) {
    asm volatile("mma.sync.aligned.m16n8k16.row.col.f32.bf16.bf16.f32 "
        "{%0,%1,%2,%3}, {%4,%5,%6,%7}, {%8,%9}, {%0,%1,%2,%3};"
        : "+f"(d[0]), "+f"(d[1]), "+f"(d[2]), "+f"(d[3])
        : "r"(a[0]), "r"(a[1]), "r"(a[2]), "r"(a[3]), "r"(b0), "r"(b1));
}
__device__ __forceinline__ float ex2(float x) {
    float y; asm("ex2.approx.ftz.f32 %0, %1;" : "=f"(y) : "f"(x)); return y;
}
__device__ __forceinline__ uint32_t packlh(float lo, float hi) {
    uint32_t d; asm("cvt.rn.bf16x2.f32 %0, %1, %2;" : "=r"(d) : "f"(hi), "f"(lo)); return d;
}

#define QSCALE (0.125f * 1.44269504f)

// ---------------------------------------------------------------------------
// Split conversions: fp32 -> [hi | lo] bf16 (K-doubled layout)
// ---------------------------------------------------------------------------
__global__ __launch_bounds__(256) void split_A(
    const float* __restrict__ X, __nv_bfloat16* __restrict__ A, int K, int M)
{
    int i = blockIdx.x * 256 + threadIdx.x;
    if (i >= M * (K / 4)) return;
    int row = i / (K / 4);
    int c = (i % (K / 4)) * 4;
    float4 x = ((const float4*)X)[i];
    float xs[4] = {x.x, x.y, x.z, x.w};
    __nv_bfloat16 h[4], l[4];
#pragma unroll
    for (int q = 0; q < 4; q++) {
        h[q] = __float2bfloat16_rn(xs[q]);
        l[q] = __float2bfloat16_rn(xs[q] - __bfloat162float(h[q]));
    }
    __nv_bfloat16* base = A + (size_t)row * 2 * K + c;
    *(uint2*)(base)     = *(uint2*)h;
    *(uint2*)(base + K) = *(uint2*)l;
}

__global__ __launch_bounds__(256) void split_W(
    const float* __restrict__ W, __nv_bfloat16* __restrict__ Bo, int N, int K)
{
    __shared__ float t[32][33];
    int tx = threadIdx.x, ty = threadIdx.y;
    int n0 = blockIdx.x * 32, k0 = blockIdx.y * 32;
#pragma unroll
    for (int j = 0; j < 4; j++)
        t[ty + 8 * j][tx] = W[(size_t)(k0 + ty + 8 * j) * N + n0 + tx];
    __syncthreads();
#pragma unroll
    for (int j = 0; j < 4; j++) {
        float x = t[tx][ty + 8 * j];
        __nv_bfloat16 h = __float2bfloat16_rn(x);
        __nv_bfloat16 l = __float2bfloat16_rn(x - __bfloat162float(h));
        size_t o = (size_t)(n0 + ty + 8 * j) * 2 * K + k0 + tx;
        Bo[o]     = h;
        Bo[o + K] = l;
    }
}

// ---------------------------------------------------------------------------
// HMMA GEMM with fused 3-pass split:
//   D = Ahi.Bhi^T + Alo.Bhi^T + Ahi.Blo^T  (fragments loaded once per k16)
// CTA tile 128x128, BK=32 (real K), 2-stage cp.async, 8 warps (2M x 4N),
// warp tile 64x32.
//   QKV_EPI=0: C = fp32 (.. + bias)        (out projection -> d_out)
//   QKV_EPI=1: bf16 hi/lo pre-split head-major Qsp/Ksp/Vsp, Q scaled
// ---------------------------------------------------------------------------
#define BM 128
#define BN 128
#define BK 32
#define LDS 80
#define TILE (BM * LDS)            // 10240 per operand tile
#define STG (4 * TILE)             // Ahi|Alo|Bhi|Blo = 40960
#define GEMM_SMEM (2 * STG)        // 81920

template <int QKV_EPI>
__global__ __launch_bounds__(256, 2) void hmma_gemm(
    const __nv_bfloat16* __restrict__ A, const __nv_bfloat16* __restrict__ B,
    const float* __restrict__ bias, float* __restrict__ C,
    __nv_bfloat16* __restrict__ Qsp, __nv_bfloat16* __restrict__ Ksp,
    __nv_bfloat16* __restrict__ Vsp, int N)
{
    extern __shared__ char sm[];
    uint32_t sb = smem_u32(sm);
    const int tid = threadIdx.x;
    const int lane = tid & 31;
    const int wid = tid >> 5;
    const int bm = blockIdx.y * BM;
    const int bn = blockIdx.x * BN;
    const int wm = (wid & 1) * 64;     // warp M offset (2 warps in M)
    const int wn = (wid >> 1) * 32;    // warp N offset (4 warps in N)

    float acc[4][4][4];                // [m16][n8][frag]
#pragma unroll
    for (int mt = 0; mt < 4; mt++)
#pragma unroll
        for (int nb = 0; nb < 4; nb++)
#pragma unroll
            for (int q = 0; q < 4; q++) acc[mt][nb][q] = 0.0f;

    // stage layout: Ahi | Alo | Bhi | Blo, each 128 rows x 32 cols (LDS=80 stride)
#define LOAD_STAGE(stg, k0) do {                                               \
    uint32_t so_ = sb + (stg) * STG;                                           \
    _Pragma("unroll")                                                          \
    for (int i_ = 0; i_ < 2; i_++) {                                           \
        int e_ = tid + i_ * 256;                                               \
        int r_ = e_ >> 2, c_ = e_ & 3;                                         \
        const __nv_bfloat16* ar_ = A + (size_t)(bm + r_) * K2 + (k0) + c_ * 8; \
        const __nv_bfloat16* br_ = B + (size_t)(bn + r_) * K2 + (k0) + c_ * 8; \
        cpasync16(so_ + r_ * LDS + c_ * 16, ar_);                              \
        cpasync16(so_ + TILE + r_ * LDS + c_ * 16, ar_ + HID);                 \
        cpasync16(so_ + 2 * TILE + r_ * LDS + c_ * 16, br_);                   \
        cpasync16(so_ + 3 * TILE + r_ * LDS + c_ * 16, br_ + HID);             \
    }                                                                          \
} while (0)

    LOAD_STAGE(0, 0);
    asm volatile("cp.async.commit_group;" ::: "memory");
    LOAD_STAGE(1, BK);
    asm volatile("cp.async.commit_group;" ::: "memory");

    const int NIT = HID / BK;          // 32
    for (int it = 0; it < NIT; it++) {
        asm volatile("cp.async.wait_group 1;" ::: "memory");
        __syncthreads();

        uint32_t sA = sb + (it & 1) * STG;
        uint32_t sB = sA + 2 * TILE;
#pragma unroll
        for (int ks = 0; ks < 2; ks++) {
            // B fragments for this k16: hi and lo, both n16-chunks (live)
            uint32_t bh[2][4], bl[2][4];
#pragma unroll
            for (int nb2 = 0; nb2 < 2; nb2++) {
                uint32_t baddr = sB + (wn + nb2 * 16 + (lane & 7) + ((lane >> 4) << 3)) * LDS
                               + ks * 32 + (((lane >> 3) & 1) << 4);
                ldm_x4(bh[nb2], baddr);
                ldm_x4(bl[nb2], baddr + TILE);
            }
            // stream A fragments, 3 passes from registers
#pragma unroll
            for (int mt = 0; mt < 4; mt++) {
                uint32_t ah[4], al[4];
                uint32_t aaddr = sA + (wm + mt * 16 + (lane & 15)) * LDS
                               + ks * 32 + ((lane >> 4) << 4);
                ldm_x4(ah, aaddr);
                ldm_x4(al, aaddr + TILE);
                mma16816(acc[mt][0], ah, bh[0][0], bh[0][1]);
                mma16816(acc[mt][1], ah, bh[0][2], bh[0][3]);
                mma16816(acc[mt][2], ah, bh[1][0], bh[1][1]);
                mma16816(acc[mt][3], ah, bh[1][2], bh[1][3]);
                mma16816(acc[mt][0], al, bh[0][0], bh[0][1]);
                mma16816(acc[mt][1], al, bh[0][2], bh[0][3]);
                mma16816(acc[mt][2], al, bh[1][0], bh[1][1]);
                mma16816(acc[mt][3], al, bh[1][2], bh[1][3]);
                mma16816(acc[mt][0], ah, bl[0][0], bl[0][1]);
                mma16816(acc[mt][1], ah, bl[0][2], bl[0][3]);
                mma16816(acc[mt][2], ah, bl[1][0], bl[1][1]);
                mma16816(acc[mt][3], ah, bl[1][2], bl[1][3]);
            }
        }

        __syncthreads();
        if (it + 2 < NIT) LOAD_STAGE(it & 1, (it + 2) * BK);
        asm volatile("cp.async.commit_group;" ::: "memory");
    }

    const int g = lane >> 2;
    const int tg = lane & 3;
#pragma unroll
    for (int mt = 0; mt < 4; mt++) {
        int row0 = bm + wm + mt * 16 + g;
#pragma unroll
        for (int nb = 0; nb < 4; nb++) {
            int col = bn + wn + nb * 8 + tg * 2;
            float bx = bias[col], by = bias[col + 1];
            float v00 = acc[mt][nb][0] + bx, v01 = acc[mt][nb][1] + by;
            float v10 = acc[mt][nb][2] + bx, v11 = acc[mt][nb][3] + by;
            if (QKV_EPI == 0) {
                float2 o0 = {v00, v01}, o1 = {v10, v11};
                *(float2*)(C + (size_t)row0 * N + col) = o0;
                *(float2*)(C + (size_t)(row0 + 8) * N + col) = o1;
            } else {
                int third = col >> 10;
                int head = (col >> 6) & 15;
                int dim = col & 63;
                __nv_bfloat16* base = (third == 0) ? Qsp : (third == 1) ? Ksp : Vsp;
                if (third == 0) { v00 *= QSCALE; v01 *= QSCALE; v10 *= QSCALE; v11 *= QSCALE; }
#pragma unroll
                for (int rr = 0; rr < 2; rr++) {
                    int m = row0 + rr * 8;
                    float va = rr ? v10 : v00, vb = rr ? v11 : v01;
                    int b_ = m >> 11, s_ = m & 2047;
                    size_t off = ((size_t)((b_ * NHEAD + head) * S_LEN + s_) << 7) + dim;
                    __nv_bfloat162 h2 = __floats2bfloat162_rn(va, vb);
                    uint32_t lo2 = packlh(va - __low2float(h2), vb - __high2float(h2));
                    *(uint32_t*)(base + off) = *(uint32_t*)&h2;
                    *(uint32_t*)(base + off + 64) = lo2;
                }
            }
        }
    }
#undef LOAD_STAGE
}

// ---------------------------------------------------------------------------
// HMMA flash attention (causal): cp.async 3-stage pipeline on pre-split bf16.
// CTA = 128 q rows x (b,h); 8 warps x 16 rows; 64-key tiles.
// ---------------------------------------------------------------------------
#define FROW 272
#define QBYTES   (128 * FROW)
#define KVSTAGE  (128 * FROW)
#define VOFF     (64 * FROW)
#define FA_SMEM  (QBYTES + 3 * KVSTAGE)

__global__ __launch_bounds__(256) void flash_attn_mma(
    const __nv_bfloat16* __restrict__ Qsp, const __nv_bfloat16* __restrict__ Ksp,
    const __nv_bfloat16* __restrict__ Vsp, __nv_bfloat16* __restrict__ Actx)
{
    extern __shared__ char smem[];
    uint32_t sb = smem_u32(smem);
    const int Tq = (S_LEN / 128 - 1) - blockIdx.x;   // heavy tiles first
    const int h = blockIdx.y, b = blockIdx.z;
    const int tid = threadIdx.x, lane = tid & 31, w = tid >> 5;
    const int g = lane >> 2, tg = lane & 3;
    const size_t bh = (size_t)(b * NHEAD + h) * S_LEN;
    const int KT = 2 * Tq + 2;

#pragma unroll
    for (int i = 0; i < 8; i++) {
        int e = tid + i * 256, r = e >> 4, c = e & 15;
        cpasync16(sb + r * FROW + c * 16,
                  Qsp + ((bh + Tq * 128 + r) << 7) + c * 8);
    }
#define LOAD_KV(slot, t) do {                                                  \
    uint32_t st_ = sb + QBYTES + (slot) * KVSTAGE;                             \
    _Pragma("unroll")                                                          \
    for (int i_ = 0; i_ < 4; i_++) {                                           \
        int e_ = tid + i_ * 256;                                               \
        int r_ = e_ >> 4, c_ = e_ & 15;                                        \
        size_t src_ = ((bh + (t) * 64 + r_) << 7) + c_ * 8;                    \
        cpasync16(st_ + r_ * FROW + c_ * 16, Ksp + src_);                      \
        cpasync16(st_ + VOFF + r_ * FROW + c_ * 16, Vsp + src_);               \
    }                                                                          \
} while (0)
    LOAD_KV(0, 0);
    asm volatile("cp.async.commit_group;" ::: "memory");
    if (1 < KT) LOAD_KV(1, 1);
    asm volatile("cp.async.commit_group;" ::: "memory");
    if (2 < KT) LOAD_KV(2, 2);
    asm volatile("cp.async.commit_group;" ::: "memory");

    float m0 = -1e30f, m1 = -1e30f, l0 = 0.0f, l1 = 0.0f;
    float acc[8][4];
#pragma unroll
    for (int nb = 0; nb < 8; nb++)
#pragma unroll
        for (int q = 0; q < 4; q++) acc[nb][q] = 0.0f;

    int slot = 0;
    for (int kt = 0; kt < KT; kt++) {
        asm volatile("cp.async.wait_group 2;" ::: "memory");
        __syncthreads();

        const uint32_t stK = sb + QBYTES + slot * KVSTAGE;
        const uint32_t stV = stK + VOFF;
        const int wrow = Tq * 128 + w * 16;
        const bool skip = (kt * 64 > wrow + 15);

        if (!skip) {
            float s[8][4];
#pragma unroll
            for (int nb = 0; nb < 8; nb++)
#pragma unroll
                for (int q = 0; q < 4; q++) s[nb][q] = 0.0f;

#pragma unroll
            for (int ks = 0; ks < 4; ks++) {
                uint32_t ah[4], al[4];
                uint32_t qaddr = sb + (w * 16 + (lane & 15)) * FROW
                               + ks * 32 + ((lane >> 4) << 4);
                ldm_x4(ah, qaddr);
                ldm_x4(al, qaddr + 128);
#pragma unroll
                for (int nb2 = 0; nb2 < 4; nb2++) {
                    uint32_t bk[4];
                    uint32_t kaddr = stK
                                   + (nb2 * 16 + (lane & 7) + ((lane >> 4) << 3)) * FROW
                                   + ks * 32 + (((lane >> 3) & 1) << 4);
                    ldm_x4(bk, kaddr);
                    mma16816(s[nb2 * 2],     ah, bk[0], bk[1]);
                    mma16816(s[nb2 * 2 + 1], ah, bk[2], bk[3]);
                    mma16816(s[nb2 * 2],     al, bk[0], bk[1]);
                    mma16816(s[nb2 * 2 + 1], al, bk[2], bk[3]);
                    ldm_x4(bk, kaddr + 128);
                    mma16816(s[nb2 * 2],     ah, bk[0], bk[1]);
                    mma16816(s[nb2 * 2 + 1], ah, bk[2], bk[3]);
                }
            }

            if (kt * 64 + 63 > wrow) {
                int r0g = wrow + g, r1g = r0g + 8;
#pragma unroll
                for (int nb = 0; nb < 8; nb++) {
                    int kc = kt * 64 + nb * 8 + tg * 2;
                    if (kc     > r0g) s[nb][0] = -1e30f;
                    if (kc + 1 > r0g) s[nb][1] = -1e30f;
                    if (kc     > r1g) s[nb][2] = -1e30f;
                    if (kc + 1 > r1g) s[nb][3] = -1e30f;
                }
            }

            float mx0 = -1e30f, mx1 = -1e30f;
#pragma unroll
            for (int nb = 0; nb < 8; nb++) {
                mx0 = fmaxf(mx0, fmaxf(s[nb][0], s[nb][1]));
                mx1 = fmaxf(mx1, fmaxf(s[nb][2], s[nb][3]));
            }
            mx0 = fmaxf(mx0, __shfl_xor_sync(0xffffffffu, mx0, 1));
            mx0 = fmaxf(mx0, __shfl_xor_sync(0xffffffffu, mx0, 2));
            mx1 = fmaxf(mx1, __shfl_xor_sync(0xffffffffu, mx1, 1));
            mx1 = fmaxf(mx1, __shfl_xor_sync(0xffffffffu, mx1, 2));
            float mn0 = fmaxf(m0, mx0), mn1 = fmaxf(m1, mx1);
            float sc0 = ex2(m0 - mn0), sc1 = ex2(m1 - mn1);
            float sum0 = 0.0f, sum1 = 0.0f;
            uint32_t aphi[4][4], aplo[4][4];
#pragma unroll
            for (int ks = 0; ks < 4; ks++)
#pragma unroll
                for (int hf = 0; hf < 2; hf++) {
                    int nb = ks * 2 + hf;
                    float p0 = ex2(s[nb][0] - mn0);
                    float p1 = ex2(s[nb][1] - mn0);
                    float p2 = ex2(s[nb][2] - mn1);
                    float p3 = ex2(s[nb][3] - mn1);
                    sum0 += p0 + p1; sum1 += p2 + p3;
                    __nv_bfloat162 t01 = __floats2bfloat162_rn(p0, p1);
                    __nv_bfloat162 t23 = __floats2bfloat162_rn(p2, p3);
                    aphi[ks][hf * 2]     = *(uint32_t*)&t01;
                    aphi[ks][hf * 2 + 1] = *(uint32_t*)&t23;
                    aplo[ks][hf * 2]     = packlh(p0 - __low2float(t01), p1 - __high2float(t01));
                    aplo[ks][hf * 2 + 1] = packlh(p2 - __low2float(t23), p3 - __high2float(t23));
                }
            sum0 += __shfl_xor_sync(0xffffffffu, sum0, 1);
            sum0 += __shfl_xor_sync(0xffffffffu, sum0, 2);
            sum1 += __shfl_xor_sync(0xffffffffu, sum1, 1);
            sum1 += __shfl_xor_sync(0xffffffffu, sum1, 2);
            l0 = l0 * sc0 + sum0; l1 = l1 * sc1 + sum1;
            m0 = mn0; m1 = mn1;
#pragma unroll
            for (int nb = 0; nb < 8; nb++) {
                acc[nb][0] *= sc0; acc[nb][1] *= sc0;
                acc[nb][2] *= sc1; acc[nb][3] *= sc1;
            }

#pragma unroll
            for (int ks = 0; ks < 4; ks++) {
#pragma unroll
                for (int nb2 = 0; nb2 < 4; nb2++) {
                    uint32_t bv[4];
                    uint32_t vaddr = stV
                                   + (ks * 16 + ((lane >> 3) & 1) * 8 + (lane & 7)) * FROW
                                   + nb2 * 32 + ((lane >> 4) << 4);
                    ldm_x4_t(bv, vaddr);
                    mma16816(acc[nb2 * 2],     aphi[ks], bv[0], bv[1]);
                    mma16816(acc[nb2 * 2 + 1], aphi[ks], bv[2], bv[3]);
                    mma16816(acc[nb2 * 2],     aplo[ks], bv[0], bv[1]);
                    mma16816(acc[nb2 * 2 + 1], aplo[ks], bv[2], bv[3]);
                    ldm_x4_t(bv, vaddr + 128);
                    mma16816(acc[nb2 * 2],     aphi[ks], bv[0], bv[1]);
                    mma16816(acc[nb2 * 2 + 1], aphi[ks], bv[2], bv[3]);
                }
            }
        }

        __syncthreads();
        if (kt + 3 < KT) LOAD_KV(slot, kt + 3);
        asm volatile("cp.async.commit_group;" ::: "memory");
        slot = (slot == 2) ? 0 : slot + 1;
    }

    // ---- write ctx directly in g_A split layout [row, hi|lo] ----
    float inv0 = 1.0f / l0, inv1 = 1.0f / l1;
    int row0 = b * S_LEN + Tq * 128 + w * 16 + g;
#pragma unroll
    for (int nb = 0; nb < 8; nb++) {
        int col = h * 64 + nb * 8 + tg * 2;
#pragma unroll
        for (int rr = 0; rr < 2; rr++) {
            float va = (rr ? acc[nb][2] * inv1 : acc[nb][0] * inv0);
            float vb = (rr ? acc[nb][3] * inv1 : acc[nb][1] * inv0);
            __nv_bfloat16* base = Actx + (size_t)(row0 + rr * 8) * K2 + col;
            __nv_bfloat162 h2 = __floats2bfloat162_rn(va, vb);
            uint32_t lo2 = packlh(va - __low2float(h2), vb - __high2float(h2));
            *(uint32_t*)(base)       = *(uint32_t*)&h2;
            *(uint32_t*)(base + HID) = lo2;
        }
    }
}

// ---------------------------------------------------------------------------
// Launch
// ---------------------------------------------------------------------------
extern "C" void kernel_launch(void* const* d_in, const int* in_sizes, int n_in,
                              void* d_out, int out_size)
{
    const float* hidden = (const float*)d_in[0];
    const float* W_qkv = (const float*)d_in[2];
    const float* b_qkv = (const float*)d_in[3];
    const float* W_out = (const float*)d_in[4];
    const float* b_out = (const float*)d_in[5];
    float* out = (float*)d_out;

    __nv_bfloat16 *A_d, *Bq_d, *Bo_d, *Qsp, *Ksp, *Vsp;
    cudaGetSymbolAddress((void**)&A_d, g_A);
    cudaGetSymbolAddress((void**)&Bq_d, g_Bqkv);
    cudaGetSymbolAddress((void**)&Bo_d, g_Bout);
    cudaGetSymbolAddress((void**)&Qsp, g_Qsp);
    cudaGetSymbolAddress((void**)&Ksp, g_Ksp);
    cudaGetSymbolAddress((void**)&Vsp, g_Vsp);

    cudaFuncSetAttribute(hmma_gemm<0>, cudaFuncAttributeMaxDynamicSharedMemorySize, GEMM_SMEM);
    cudaFuncSetAttribute(hmma_gemm<1>, cudaFuncAttributeMaxDynamicSharedMemorySize, GEMM_SMEM);
    cudaFuncSetAttribute(flash_attn_mma, cudaFuncAttributeMaxDynamicSharedMemorySize, FA_SMEM);

    // 1) Split inputs (hi|lo layouts)
    int n4 = MROWS * (HID / 4);
    split_A<<<(n4 + 255) / 256, 256>>>(hidden, A_d, HID, MROWS);
    split_W<<<dim3(3 * HID / 32, HID / 32), dim3(32, 8)>>>(W_qkv, Bq_d, 3 * HID, HID);
    split_W<<<dim3(HID / 32, HID / 32), dim3(32, 8)>>>(W_out, Bo_d, HID, HID);

    // 2) QKV projection -> pre-split head-major Qsp/Ksp/Vsp (Q scaled)
    hmma_gemm<1><<<dim3(3 * HID / BN, MROWS / BM), 256, GEMM_SMEM>>>(
        A_d, Bq_d, b_qkv, nullptr, Qsp, Ksp, Vsp, 3 * HID);

    // 3) Flash attention -> ctx directly in g_A split layout
    flash_attn_mma<<<dim3(S_LEN / 128, NHEAD, BATCH), 256, FA_SMEM>>>(
        Qsp, Ksp, Vsp, A_d);

    // 4) Output projection -> d_out
    hmma_gemm<0><<<dim3(HID / BN, MROWS / BM), 256, GEMM_SMEM>>>(
        A_d, Bo_d, b_out, out, nullptr, nullptr, nullptr, HID);
}